// round 12
// baseline (speedup 1.0000x reference)
#include <cuda_runtime.h>
#include <cuda_bf16.h>
#include <math.h>
#include <stdint.h>

#define B_    4
#define S_    2048
#define D_    1024
#define H_    16
#define HD_   64
#define E_    8
#define F_    4096
#define FS_   2048
#define T_    8192
#define CAP_  2560
#define KT_   16384   // K * T slots

// ---------------- scratch (static device globals; no allocations) ----------
__device__ float g_qkv [3 * T_ * D_];     // q | k | v contiguous
__device__ float g_vt  [T_ * D_];
__device__ float g_x2  [T_ * D_];
__device__ float g_xn2 [T_ * D_];
__device__ float g_eo  [E_ * CAP_ * D_];
__device__ float g_shout[T_ * D_];
__device__ float g_bqkv[3 * D_];
__device__ float g_wqkv3[3 * D_ * D_];    // contiguous fp32 qkv weights
__device__ int   g_eidx[KT_];
__device__ int   g_pos [KT_];
__device__ int   g_cnt [E_];
__device__ float g_gate[KT_];
// bf16 hi/lo plane tensors: activations k-major [M][K/2] (u32 = bf16x2 k-pair)
__device__ uint32_t g_xn1h [T_ * D_ / 2],        g_xn1l [T_ * D_ / 2];
__device__ uint32_t g_attnh[T_ * D_ / 2],        g_attnl[T_ * D_ / 2];
__device__ uint32_t g_xn2h [T_ * D_ / 2],        g_xn2l [T_ * D_ / 2];
__device__ uint32_t g_disph[E_ * CAP_ * D_ / 2], g_displ[E_ * CAP_ * D_ / 2];
__device__ uint32_t g_hbh  [E_ * CAP_ * F_ / 2], g_hbl  [E_ * CAP_ * F_ / 2];
__device__ uint32_t g_shhh [T_ * FS_ / 2],       g_shhl [T_ * FS_ / 2];

// ---------------- helpers ---------------------------------------------------
__device__ __forceinline__ void split2(float x, float y,
                                       uint32_t& hi, uint32_t& lo)
{
    __nv_bfloat16 hx = __float2bfloat16(x);
    __nv_bfloat16 hy = __float2bfloat16(y);
    float rx = x - __bfloat162float(hx);
    float ry = y - __bfloat162float(hy);
    __nv_bfloat162 h2; h2.x = hx; h2.y = hy;
    __nv_bfloat162 l2; l2.x = __float2bfloat16(rx); l2.y = __float2bfloat16(ry);
    hi = *(uint32_t*)&h2;
    lo = *(uint32_t*)&l2;
}

__device__ __forceinline__ void mma16(float* acc,
                                      uint32_t a0, uint32_t a1, uint32_t a2, uint32_t a3,
                                      uint32_t b0, uint32_t b1)
{
    asm("mma.sync.aligned.m16n8k16.row.col.f32.bf16.bf16.f32 "
        "{%0,%1,%2,%3},{%4,%5,%6,%7},{%8,%9},{%0,%1,%2,%3};"
        : "+f"(acc[0]), "+f"(acc[1]), "+f"(acc[2]), "+f"(acc[3])
        : "r"(a0), "r"(a1), "r"(a2), "r"(a3), "r"(b0), "r"(b1));
}

__device__ __forceinline__ void ldsm4(uint32_t& r0, uint32_t& r1,
                                      uint32_t& r2, uint32_t& r3, uint32_t addr)
{
    asm volatile("ldmatrix.sync.aligned.m8n8.x4.shared.b16 {%0,%1,%2,%3}, [%4];"
                 : "=r"(r0), "=r"(r1), "=r"(r2), "=r"(r3) : "r"(addr));
}

__device__ __forceinline__ void cpasync16(uint32_t dst, const void* src)
{
    asm volatile("cp.async.cg.shared.global [%0], [%1], 16;"
                 :: "r"(dst), "l"(src));
}
#define CP_COMMIT() asm volatile("cp.async.commit_group;" ::: "memory")
#define CP_WAIT0()  asm volatile("cp.async.wait_group 0;" ::: "memory")

// ---------------- QKV weight/bias concat ------------------------------------
__global__ void __launch_bounds__(256) wconcat3_kernel(
    const float* __restrict__ a, const float* __restrict__ b,
    const float* __restrict__ c, float* __restrict__ out)
{
    const long i = (long)blockIdx.x * 1024 + threadIdx.x * 4;
    const float* src = blockIdx.y == 0 ? a : (blockIdx.y == 1 ? b : c);
    *(float4*)&out[(long)blockIdx.y * D_ * D_ + i] = *(const float4*)&src[i];
}
__global__ void __launch_bounds__(256) concat3_kernel(
    const float* __restrict__ a, const float* __restrict__ b,
    const float* __restrict__ c, float* __restrict__ out)
{
    const int i = blockIdx.x * 256 + threadIdx.x;
    const float* src = blockIdx.y == 0 ? a : (blockIdx.y == 1 ? b : c);
    out[blockIdx.y * D_ + i] = src[i];
}

// ---------------- bf16x3 tensor-core GEMM ----------------------------------
// CTA 128x128, warp tile 64x32, BK=32 (16 k-pairs), 2-stage, 1 barrier/iter.
// A: pre-split bf16 planes [M][K/2], filled via cp.async.
// B: raw fp32 [K][N], split in-kernel (LDG held over compute, STS after).
// Smem planes pitch 20 (conflict-free ldmatrix).
#define PWu  20
#define PLW  (128 * PWu)           // 2560 u32 per plane
#define STW  (4 * PLW)             // 10240 u32 / stage
#define TC_SMEM (2 * STW * 4)      // 81920 B

#define OF_AH 0
#define OF_AL PLW
#define OF_BH (2 * PLW)
#define OF_BL (3 * PLW)

__device__ __forceinline__ void fillA(
    uint32_t sb, const uint32_t* __restrict__ Ah, const uint32_t* __restrict__ Al,
    int kt, int K2, int m0, int tid)
{
    #pragma unroll
    for (int i = 0; i < 2; i++) {
        const int lin = i * 256 + tid;
        const int row = lin >> 2, ch = (lin & 3) * 4;
        const long src = (long)(m0 + row) * K2 + kt * 16 + ch;
        const uint32_t d = sb + (uint32_t)(row * PWu + ch) * 4;
        cpasync16(d + OF_AH * 4, Ah + src);
        cpasync16(d + OF_AL * 4, Al + src);
    }
}

// load B tile (32 k x 128 n) for tile kt into registers
__device__ __forceinline__ void loadB(
    const float* __restrict__ Bw, int kt, int N, int n0, int tid,
    float4 r0[2], float4 r1[2])
{
    const int kp = tid >> 5;             // 0..7
    const int n4 = (tid & 31) * 4;
    #pragma unroll
    for (int i = 0; i < 2; i++) {
        const long k0 = (long)(kt * 32 + 2 * (kp + i * 8));
        r0[i] = *(const float4*)(Bw + k0 * N + n0 + n4);
        r1[i] = *(const float4*)(Bw + (k0 + 1) * N + n0 + n4);
    }
}

// split + store B regs into n-major smem planes
__device__ __forceinline__ void stsB(uint32_t sb, int tid,
                                     const float4 r0[2], const float4 r1[2])
{
    const int kp = tid >> 5;
    const int n4 = (tid & 31) * 4;
    #pragma unroll
    for (int i = 0; i < 2; i++) {
        const int kpi = kp + i * 8;
        uint32_t h[4], l[4];
        split2(r0[i].x, r1[i].x, h[0], l[0]);
        split2(r0[i].y, r1[i].y, h[1], l[1]);
        split2(r0[i].z, r1[i].z, h[2], l[2]);
        split2(r0[i].w, r1[i].w, h[3], l[3]);
        #pragma unroll
        for (int j = 0; j < 4; j++) {
            const uint32_t off = (uint32_t)(((n4 + j) * PWu + kpi) * 4);
            asm volatile("st.shared.b32 [%0], %1;" :: "r"(sb + off + OF_BH * 4), "r"(h[j]));
            asm volatile("st.shared.b32 [%0], %1;" :: "r"(sb + off + OF_BL * 4), "r"(l[j]));
        }
    }
}

__device__ __forceinline__ void kslice_mma(
    uint32_t sb, int kp0, int wm, int wn,
    uint32_t a_lo, uint32_t b_lo, float acc[4][4][4])
{
    uint32_t bh[4][2], bl[4][2];
    #pragma unroll
    for (int p = 0; p < 2; p++) {
        const uint32_t base = sb + (uint32_t)(((wn * 32 + p * 16) * PWu + kp0) * 4) + b_lo;
        ldsm4(bh[2*p][0], bh[2*p][1], bh[2*p+1][0], bh[2*p+1][1], base + OF_BH * 4);
        ldsm4(bl[2*p][0], bl[2*p][1], bl[2*p+1][0], bl[2*p+1][1], base + OF_BL * 4);
    }
    #pragma unroll
    for (int mt = 0; mt < 4; mt++) {
        const uint32_t abase = sb + (uint32_t)(((wm * 64 + mt * 16) * PWu + kp0) * 4) + a_lo;
        uint32_t ah0, ah1, ah2, ah3, al0, al1, al2, al3;
        ldsm4(ah0, ah1, ah2, ah3, abase + OF_AH * 4);
        ldsm4(al0, al1, al2, al3, abase + OF_AL * 4);
        #pragma unroll
        for (int nt = 0; nt < 4; nt++)
            mma16(acc[mt][nt], ah0, ah1, ah2, ah3, bh[nt][0], bh[nt][1]);
        #pragma unroll
        for (int nt = 0; nt < 4; nt++)
            mma16(acc[mt][nt], ah0, ah1, ah2, ah3, bl[nt][0], bl[nt][1]);
        #pragma unroll
        for (int nt = 0; nt < 4; nt++)
            mma16(acc[mt][nt], al0, al1, al2, al3, bh[nt][0], bh[nt][1]);
    }
}

template<bool GELU, bool RES, bool SPLITOUT>
__global__ void __launch_bounds__(256, 2) tc_gemm(
    const uint32_t* __restrict__ Ah, const uint32_t* __restrict__ Al,
    const float* __restrict__ Bw,
    const float* __restrict__ bias, const float* __restrict__ res,
    float* __restrict__ C, uint32_t* __restrict__ Ch, uint32_t* __restrict__ Cl,
    const int* __restrict__ rowcnt,
    int Kd, int N, long sA, long sB, long sBias, long sC)
{
    extern __shared__ uint32_t smw[];
    const uint32_t sbase = (uint32_t)__cvta_generic_to_shared(smw);
    const int tid = threadIdx.x, wid = tid >> 5, lane = tid & 31;
    const int g = lane >> 2, t = lane & 3;
    const int wm = wid & 1, wn = wid >> 1;
    const int bz = blockIdx.z;
    const int m0 = blockIdx.y * 128, n0 = blockIdx.x * 128;
    if (rowcnt != nullptr && m0 >= __ldg(&rowcnt[bz])) return;

    Ah += bz * sA; Al += bz * sA;
    Bw += bz * sB;
    bias += bz * sBias;
    if (SPLITOUT) { Ch += bz * sC; Cl += bz * sC; }
    else          { C  += bz * sC; }
    const int K2 = Kd >> 1;
    const int NT = Kd >> 5;

    const uint32_t a_lo = (uint32_t)(((lane & 15) * PWu + ((lane >> 4) << 2)) * 4);
    const uint32_t b_lo = (uint32_t)(((((lane & 7) | ((lane >> 4) << 3)) * PWu)
                                     + (((lane >> 3) & 1) << 2)) * 4);

    float acc[4][4][4];
    #pragma unroll
    for (int mt = 0; mt < 4; mt++)
        #pragma unroll
        for (int nt = 0; nt < 4; nt++)
            #pragma unroll
            for (int c = 0; c < 4; c++) acc[mt][nt][c] = 0.0f;

    float4 br0[2], br1[2];
    fillA(sbase, Ah, Al, 0, K2, m0, tid);
    CP_COMMIT();
    loadB(Bw, 0, N, n0, tid, br0, br1);
    stsB(sbase, tid, br0, br1);

    int st = 0;
    for (int kt = 0; kt < NT; kt++) {
        CP_WAIT0();
        __syncthreads();
        if (kt + 1 < NT) {
            fillA(sbase + (st ^ 1) * (STW * 4), Ah, Al, kt + 1, K2, m0, tid);
            loadB(Bw, kt + 1, N, n0, tid, br0, br1);
        }
        CP_COMMIT();
        const uint32_t sb = sbase + st * (STW * 4);
        kslice_mma(sb, 0, wm, wn, a_lo, b_lo, acc);
        kslice_mma(sb, 8, wm, wn, a_lo, b_lo, acc);
        if (kt + 1 < NT)
            stsB(sbase + (st ^ 1) * (STW * 4), tid, br0, br1);
        st ^= 1;
    }

    // ---- epilogue ----
    #pragma unroll
    for (int mt = 0; mt < 4; mt++) {
        const int row = m0 + wm * 64 + mt * 16 + g;
        #pragma unroll
        for (int nt = 0; nt < 4; nt++) {
            const int col = n0 + wn * 32 + nt * 8 + t * 2;
            const float b0v = bias[col], b1v = bias[col + 1];
            float v0 = acc[mt][nt][0] + b0v;
            float v1 = acc[mt][nt][1] + b1v;
            float v2 = acc[mt][nt][2] + b0v;
            float v3 = acc[mt][nt][3] + b1v;
            if (GELU) {
                v0 *= normcdff(v0); v1 *= normcdff(v1);
                v2 *= normcdff(v2); v3 *= normcdff(v3);
            }
            if (SPLITOUT) {
                uint32_t h0, l0, h1, l1;
                split2(v0, v1, h0, l0);
                split2(v2, v3, h1, l1);
                const long p0 = (long)row * (N >> 1) + (col >> 1);
                const long p1 = (long)(row + 8) * (N >> 1) + (col >> 1);
                Ch[p0] = h0; Cl[p0] = l0;
                Ch[p1] = h1; Cl[p1] = l1;
            } else {
                const long o0 = (long)row * N + col;
                const long o1 = (long)(row + 8) * N + col;
                if (RES) {
                    const float2 r0 = *(const float2*)&res[o0];
                    const float2 r1 = *(const float2*)&res[o1];
                    v0 += r0.x; v1 += r0.y; v2 += r1.x; v3 += r1.y;
                }
                float2 w0; w0.x = v0; w0.y = v1;
                float2 w1; w1.x = v2; w1.y = v3;
                *(float2*)&C[o0] = w0;
                *(float2*)&C[o1] = w1;
            }
        }
    }
}

// ---------------- V transpose ----------------------------------------------
__global__ void __launch_bounds__(256) transpose_v(const float* __restrict__ v,
                                                   float* __restrict__ vt)
{
    __shared__ float tile[32][33];
    const int bh = blockIdx.z;
    const int b = bh >> 4, h = bh & 15;
    const int s0 = blockIdx.x * 32, d0 = blockIdx.y * 32;
    const int tx = threadIdx.x & 31, ty = threadIdx.x >> 5;
    #pragma unroll
    for (int i = 0; i < 32; i += 8)
        tile[ty + i][tx] = v[(long)(b * S_ + s0 + ty + i) * D_ + h * 64 + d0 + tx];
    __syncthreads();
    #pragma unroll
    for (int i = 0; i < 32; i += 8)
        vt[((long)bh * 64 + d0 + ty + i) * S_ + s0 + tx] = tile[tx][ty + i];
}

// ---------------- Flash attention, bf16x3 tensor cores ---------------------
#define QP 72
#define SM_QH 0
#define SM_QL (128 * QP)
#define SM_KH (2 * 128 * QP)
#define SM_KL (SM_KH + 64 * QP)
#define SM_VH (SM_KL + 64 * QP)
#define SM_VL (SM_VH + 64 * QP)
#define SM_END (SM_VL + 64 * QP)
#define ATT_SMEM (SM_END * 2 + 128)

__global__ void __launch_bounds__(256) attn_mma(
    const float* __restrict__ qg, const float* __restrict__ kg,
    const float* __restrict__ vtg, const unsigned char* __restrict__ maskg,
    uint32_t* __restrict__ oh, uint32_t* __restrict__ ol)
{
    extern __shared__ uint16_t sm16[];
    char* ms = (char*)(sm16 + SM_END);

    const int b = blockIdx.z, h = blockIdx.y, q0 = blockIdx.x * 128;
    const int tid = threadIdx.x, wq = tid >> 5, lane = tid & 31;
    const int g = lane >> 2, t4 = lane & 3;
    const float NEG = -3.402823466e38f;

    #pragma unroll
    for (int i = 0; i < 8; i++) {
        const int lin = i * 256 + tid;
        const int row = lin >> 4, c4 = (lin & 15) * 4;
        const float4 v = *(const float4*)&qg[(long)(b * S_ + q0 + row) * D_ + h * 64 + c4];
        uint32_t h0, l0, h1, l1;
        split2(v.x, v.y, h0, l0);
        split2(v.z, v.w, h1, l1);
        uint2 hv; hv.x = h0; hv.y = h1;
        uint2 lv; lv.x = l0; lv.y = l1;
        *(uint2*)&sm16[SM_QH + row * QP + c4] = hv;
        *(uint2*)&sm16[SM_QL + row * QP + c4] = lv;
    }
    __syncthreads();

    uint32_t qfh[4][4], qfl[4][4];
    {
        const int qr = wq * 16 + g;
        #pragma unroll
        for (int ks = 0; ks < 4; ks++) {
            const int kc = ks * 16 + 2 * t4;
            qfh[ks][0] = *(const uint32_t*)&sm16[SM_QH + qr * QP + kc];
            qfh[ks][1] = *(const uint32_t*)&sm16[SM_QH + (qr + 8) * QP + kc];
            qfh[ks][2] = *(const uint32_t*)&sm16[SM_QH + qr * QP + kc + 8];
            qfh[ks][3] = *(const uint32_t*)&sm16[SM_QH + (qr + 8) * QP + kc + 8];
            qfl[ks][0] = *(const uint32_t*)&sm16[SM_QL + qr * QP + kc];
            qfl[ks][1] = *(const uint32_t*)&sm16[SM_QL + (qr + 8) * QP + kc];
            qfl[ks][2] = *(const uint32_t*)&sm16[SM_QL + qr * QP + kc + 8];
            qfl[ks][3] = *(const uint32_t*)&sm16[SM_QL + (qr + 8) * QP + kc + 8];
        }
    }

    float m[2], l[2], oacc[8][4];
    m[0] = m[1] = NEG; l[0] = l[1] = 0.0f;
    #pragma unroll
    for (int j = 0; j < 8; j++)
        #pragma unroll
        for (int c = 0; c < 4; c++) oacc[j][c] = 0.0f;

    for (int kt = 0; kt < 32; kt++) {
        const int k0 = kt * 64;
        __syncthreads();
        #pragma unroll
        for (int i = 0; i < 4; i++) {
            const int lin = i * 256 + tid;
            const int row = lin >> 4, c4 = (lin & 15) * 4;
            const float4 kv = *(const float4*)&kg[(long)(b * S_ + k0 + row) * D_ + h * 64 + c4];
            const float4 vv = *(const float4*)&vtg[((long)(b * 16 + h) * 64 + row) * S_ + k0 + c4];
            uint32_t h0, l0, h1, l1;
            split2(kv.x, kv.y, h0, l0);
            split2(kv.z, kv.w, h1, l1);
            uint2 a; a.x = h0; a.y = h1;
            uint2 c; c.x = l0; c.y = l1;
            *(uint2*)&sm16[SM_KH + row * QP + c4] = a;
            *(uint2*)&sm16[SM_KL + row * QP + c4] = c;
            split2(vv.x, vv.y, h0, l0);
            split2(vv.z, vv.w, h1, l1);
            a.x = h0; a.y = h1;
            c.x = l0; c.y = l1;
            *(uint2*)&sm16[SM_VH + row * QP + c4] = a;
            *(uint2*)&sm16[SM_VL + row * QP + c4] = c;
        }
        if (tid < 64) ms[tid] = (char)maskg[b * S_ + k0 + tid];
        __syncthreads();

        float sacc[8][4];
        #pragma unroll
        for (int j = 0; j < 8; j++)
            #pragma unroll
            for (int c = 0; c < 4; c++) sacc[j][c] = 0.0f;

        #pragma unroll
        for (int ks = 0; ks < 4; ks++) {
            const int kc = ks * 16 + 2 * t4;
            uint32_t kbh[8][2], kbl[8][2];
            #pragma unroll
            for (int j = 0; j < 8; j++) {
                const int krow = (8 * j + g) * QP;
                kbh[j][0] = *(const uint32_t*)&sm16[SM_KH + krow + kc];
                kbh[j][1] = *(const uint32_t*)&sm16[SM_KH + krow + kc + 8];
                kbl[j][0] = *(const uint32_t*)&sm16[SM_KL + krow + kc];
                kbl[j][1] = *(const uint32_t*)&sm16[SM_KL + krow + kc + 8];
            }
            #pragma unroll
            for (int j = 0; j < 8; j++)
                mma16(sacc[j], qfh[ks][0], qfh[ks][1], qfh[ks][2], qfh[ks][3],
                      kbh[j][0], kbh[j][1]);
            #pragma unroll
            for (int j = 0; j < 8; j++)
                mma16(sacc[j], qfh[ks][0], qfh[ks][1], qfh[ks][2], qfh[ks][3],
                      kbl[j][0], kbl[j][1]);
            #pragma unroll
            for (int j = 0; j < 8; j++)
                mma16(sacc[j], qfl[ks][0], qfl[ks][1], qfl[ks][2], qfl[ks][3],
                      kbh[j][0], kbh[j][1]);
        }

        #pragma unroll
        for (int j = 0; j < 8; j++) {
            const int col = 8 * j + 2 * t4;
            const bool m0k = ms[col] != 0;
            const bool m1k = ms[col + 1] != 0;
            sacc[j][0] = m0k ? NEG : sacc[j][0] * 0.125f;
            sacc[j][1] = m1k ? NEG : sacc[j][1] * 0.125f;
            sacc[j][2] = m0k ? NEG : sacc[j][2] * 0.125f;
            sacc[j][3] = m1k ? NEG : sacc[j][3] * 0.125f;
        }

        #pragma unroll
        for (int r = 0; r < 2; r++) {
            float rmax = NEG;
            #pragma unroll
            for (int j = 0; j < 8; j++) {
                rmax = fmaxf(rmax, sacc[j][2 * r]);
                rmax = fmaxf(rmax, sacc[j][2 * r + 1]);
            }
            rmax = fmaxf(rmax, __shfl_xor_sync(0xffffffffu, rmax, 1));
            rmax = fmaxf(rmax, __shfl_xor_sync(0xffffffffu, rmax, 2));
            const float mnew = fmaxf(m[r], rmax);
            const float corr = expf(m[r] - mnew);
            float rsum = 0.0f;
            #pragma unroll
            for (int j = 0; j < 8; j++) {
                float p0 = expf(sacc[j][2 * r]     - mnew);
                float p1 = expf(sacc[j][2 * r + 1] - mnew);
                sacc[j][2 * r] = p0; sacc[j][2 * r + 1] = p1;
                rsum += p0 + p1;
            }
            rsum += __shfl_xor_sync(0xffffffffu, rsum, 1);
            rsum += __shfl_xor_sync(0xffffffffu, rsum, 2);
            l[r] = l[r] * corr + rsum;
            m[r] = mnew;
            #pragma unroll
            for (int j = 0; j < 8; j++) {
                oacc[j][2 * r]     *= corr;
                oacc[j][2 * r + 1] *= corr;
            }
        }

        #pragma unroll
        for (int ks = 0; ks < 4; ks++) {
            const int j0 = 2 * ks, j1 = 2 * ks + 1;
            uint32_t ph0, pl0, ph1, pl1, ph2, pl2, ph3, pl3;
            split2(sacc[j0][0], sacc[j0][1], ph0, pl0);
            split2(sacc[j0][2], sacc[j0][3], ph1, pl1);
            split2(sacc[j1][0], sacc[j1][1], ph2, pl2);
            split2(sacc[j1][2], sacc[j1][3], ph3, pl3);
            const int kc = ks * 16 + 2 * t4;
            uint32_t vfh[8][2], vfl[8][2];
            #pragma unroll
            for (int j = 0; j < 8; j++) {
                const int vrow = (8 * j + g) * QP;
                vfh[j][0] = *(const uint32_t*)&sm16[SM_VH + vrow + kc];
                vfh[j][1] = *(const uint32_t*)&sm16[SM_VH + vrow + kc + 8];
                vfl[j][0] = *(const uint32_t*)&sm16[SM_VL + vrow + kc];
                vfl[j][1] = *(const uint32_t*)&sm16[SM_VL + vrow + kc + 8];
            }
            #pragma unroll
            for (int j = 0; j < 8; j++)
                mma16(oacc[j], ph0, ph1, ph2, ph3, vfh[j][0], vfh[j][1]);
            #pragma unroll
            for (int j = 0; j < 8; j++)
                mma16(oacc[j], ph0, ph1, ph2, ph3, vfl[j][0], vfl[j][1]);
            #pragma unroll
            for (int j = 0; j < 8; j++)
                mma16(oacc[j], pl0, pl1, pl2, pl3, vfh[j][0], vfh[j][1]);
        }
    }

    const float inv0 = 1.0f / l[0], inv1 = 1.0f / l[1];
    const int row0 = q0 + wq * 16 + g;
    #pragma unroll
    for (int j = 0; j < 8; j++) {
        const int col = h * 64 + 8 * j + 2 * t4;
        uint32_t h0, l0, h1, l1;
        split2(oacc[j][0] * inv0, oacc[j][1] * inv0, h0, l0);
        split2(oacc[j][2] * inv1, oacc[j][3] * inv1, h1, l1);
        const long p0 = (long)(b * S_ + row0) * (D_ / 2) + (col >> 1);
        const long p1 = (long)(b * S_ + row0 + 8) * (D_ / 2) + (col >> 1);
        oh[p0] = h0; ol[p0] = l0;
        oh[p1] = h1; ol[p1] = l1;
    }
}

// ---------------- LayerNorm (writes split planes; optional fp32) -----------
template<bool F32OUT>
__global__ void __launch_bounds__(256) ln_kernel(const float* __restrict__ x,
                                                 const float* __restrict__ g,
                                                 const float* __restrict__ b,
                                                 float* __restrict__ outf,
                                                 uint32_t* __restrict__ outh,
                                                 uint32_t* __restrict__ outl)
{
    const int row = blockIdx.x;
    const int tid = threadIdx.x;
    const float4 v = ((const float4*)(x + (long)row * D_))[tid];

    __shared__ float red[256];
    __shared__ float s_mu, s_rstd;

    float s = v.x + v.y + v.z + v.w;
    red[tid] = s; __syncthreads();
    for (int o = 128; o > 0; o >>= 1) {
        if (tid < o) red[tid] += red[tid + o];
        __syncthreads();
    }
    if (tid == 0) s_mu = red[0] * (1.0f / D_);
    __syncthreads();
    const float mu = s_mu;

    float dx0 = v.x - mu, dx1 = v.y - mu, dx2 = v.z - mu, dx3 = v.w - mu;
    float sq = dx0*dx0 + dx1*dx1 + dx2*dx2 + dx3*dx3;
    red[tid] = sq; __syncthreads();
    for (int o = 128; o > 0; o >>= 1) {
        if (tid < o) red[tid] += red[tid + o];
        __syncthreads();
    }
    if (tid == 0) s_rstd = rsqrtf(red[0] * (1.0f / D_) + 1e-5f);
    __syncthreads();
    const float rstd = s_rstd;

    const float4 gg = ((const float4*)g)[tid];
    const float4 bb = ((const float4*)b)[tid];
    float4 o4;
    o4.x = dx0 * rstd * gg.x + bb.x;
    o4.y = dx1 * rstd * gg.y + bb.y;
    o4.z = dx2 * rstd * gg.z + bb.z;
    o4.w = dx3 * rstd * gg.w + bb.w;
    if (F32OUT)
        ((float4*)(outf + (long)row * D_))[tid] = o4;
    uint32_t h0, l0, h1, l1;
    split2(o4.x, o4.y, h0, l0);
    split2(o4.z, o4.w, h1, l1);
    uint2 hv; hv.x = h0; hv.y = h1;
    uint2 lv; lv.x = l0; lv.y = l1;
    *(uint2*)&outh[(long)row * (D_ / 2) + tid * 2] = hv;
    *(uint2*)&outl[(long)row * (D_ / 2) + tid * 2] = lv;
}

// ---------------- Router --------------------------------------------------
__global__ void __launch_bounds__(256) router_kernel(
    const float* __restrict__ xn, const float* __restrict__ wr,
    int* __restrict__ eidx, float* __restrict__ gate)
{
    const int warp = threadIdx.x >> 5, lane = threadIdx.x & 31;
    const int t = blockIdx.x * 8 + warp;
    const float* xr = xn + (long)t * D_;

    float a[E_];
    #pragma unroll
    for (int e = 0; e < E_; e++) a[e] = 0.0f;
    for (int d = lane; d < D_; d += 32) {
        const float xv = xr[d];
        const float* w = wr + d * E_;
        #pragma unroll
        for (int e = 0; e < E_; e++) a[e] += xv * w[e];
    }
    #pragma unroll
    for (int e = 0; e < E_; e++)
        #pragma unroll
        for (int o = 16; o > 0; o >>= 1)
            a[e] += __shfl_xor_sync(0xffffffffu, a[e], o);

    if (lane == 0) {
        float mx = a[0];
        #pragma unroll
        for (int e = 1; e < E_; e++) mx = fmaxf(mx, a[e]);
        float ex[E_];
        #pragma unroll
        for (int e = 0; e < E_; e++) ex[e] = expf(a[e] - mx);
        int i0 = 0; float v0 = ex[0];
        #pragma unroll
        for (int e = 1; e < E_; e++) if (ex[e] > v0) { v0 = ex[e]; i0 = e; }
        int i1 = -1; float v1 = -1.0f;
        #pragma unroll
        for (int e = 0; e < E_; e++)
            if (e != i0 && ex[e] > v1) { v1 = ex[e]; i1 = e; }
        const float inv = 1.0f / (v0 + v1);
        eidx[t]       = i0; gate[t]       = v0 * inv;
        eidx[T_ + t]  = i1; gate[T_ + t]  = v1 * inv;
    }
}

// ---------------- Single-pass slot-major capacity scan ---------------------
__global__ void __launch_bounds__(256) scan_kernel(const int* __restrict__ eidx,
                                                   int* __restrict__ pos,
                                                   int* __restrict__ cnt)
{
    const int e = blockIdx.x;
    const int tid = threadIdx.x;
    const int base = tid * 64;

    int lc = 0;
    #pragma unroll 8
    for (int j = 0; j < 64; j++)
        lc += (eidx[base + j] == e) ? 1 : 0;

    __shared__ int sd[256];
    sd[tid] = lc;
    __syncthreads();
    for (int o = 1; o < 256; o <<= 1) {
        int v = (tid >= o) ? sd[tid - o] : 0;
        __syncthreads();
        sd[tid] += v;
        __syncthreads();
    }
    int run = sd[tid] - lc;
    #pragma unroll 8
    for (int j = 0; j < 64; j++) {
        if (eidx[base + j] == e) pos[base + j] = run++;
    }
    if (tid == 255) cnt[e] = sd[255] < CAP_ ? sd[255] : CAP_;
}

__global__ void __launch_bounds__(256) zero_kernel(uint4* __restrict__ p, int n4)
{
    const int i = blockIdx.x * 256 + threadIdx.x;
    if (i < n4) { uint4 z; z.x = z.y = z.z = z.w = 0; p[i] = z; }
}

__global__ void __launch_bounds__(256) dispatch_kernel(
    const uint32_t* __restrict__ xnh, const uint32_t* __restrict__ xnl,
    const int* __restrict__ eidx, const int* __restrict__ pos,
    uint32_t* __restrict__ dh, uint32_t* __restrict__ dl)
{
    const int s = blockIdx.x;
    const int p = pos[s];
    if (p >= CAP_) return;
    const int e = eidx[s];
    const int t = s & (T_ - 1);
    const long src = (long)t * (D_ / 2);
    const long dst = ((long)e * CAP_ + p) * (D_ / 2);
    const uint2* sh = (const uint2*)(xnh + src);
    const uint2* sl = (const uint2*)(xnl + src);
    uint2* th = (uint2*)(dh + dst);
    uint2* tl = (uint2*)(dl + dst);
    th[threadIdx.x] = sh[threadIdx.x];
    tl[threadIdx.x] = sl[threadIdx.x];
}

__global__ void __launch_bounds__(256) combine_kernel(
    const float* __restrict__ x2, const float* __restrict__ shout,
    const float* __restrict__ eo, const int* __restrict__ eidx,
    const int* __restrict__ pos, const float* __restrict__ gate,
    float* __restrict__ out)
{
    const int t = blockIdx.x;
    const int p0 = pos[t], p1 = pos[T_ + t];
    const float g0 = gate[t]      * (p0 < CAP_ ? 1.0f : 0.0f);
    const float g1 = gate[T_ + t] * (p1 < CAP_ ? 1.0f : 0.0f);
    const long o0 = ((long)eidx[t]      * CAP_ + min(p0, CAP_ - 1)) * D_;
    const long o1 = ((long)eidx[T_ + t] * CAP_ + min(p1, CAP_ - 1)) * D_;

    const int c = threadIdx.x;
    float4 a = ((const float4*)(x2 + (long)t * D_))[c];
    float4 s = ((const float4*)(shout + (long)t * D_))[c];
    float4 r0 = ((const float4*)(eo + o0))[c];
    float4 r1 = ((const float4*)(eo + o1))[c];
    float4 o;
    o.x = a.x + s.x + g0 * r0.x + g1 * r1.x;
    o.y = a.y + s.y + g0 * r0.y + g1 * r1.y;
    o.z = a.z + s.z + g0 * r0.z + g1 * r1.z;
    o.w = a.w + s.w + g0 * r0.w + g1 * r1.w;
    ((float4*)(out + (long)t * D_))[c] = o;
}

// ---------------------------------------------------------------------------
extern "C" void kernel_launch(void* const* d_in, const int* in_sizes, int n_in,
                              void* d_out, int out_size)
{
    const float* x   = (const float*)d_in[0];
    const unsigned char* mask = (const unsigned char*)d_in[1];
    const float* ln1g = (const float*)d_in[2];
    const float* ln1b = (const float*)d_in[3];
    const float* wq = (const float*)d_in[4];  const float* bq = (const float*)d_in[5];
    const float* wk = (const float*)d_in[6];  const float* bk = (const float*)d_in[7];
    const float* wv = (const float*)d_in[8];  const float* bv = (const float*)d_in[9];
    const float* wo = (const float*)d_in[10]; const float* bo = (const float*)d_in[11];
    const float* ln2g = (const float*)d_in[12];
    const float* ln2b = (const float*)d_in[13];
    const float* wr = (const float*)d_in[14];
    const float* w1 = (const float*)d_in[15]; const float* b1 = (const float*)d_in[16];
    const float* w2 = (const float*)d_in[17]; const float* b2 = (const float*)d_in[18];
    const float* ws1 = (const float*)d_in[19]; const float* bs1 = (const float*)d_in[20];
    const float* ws2 = (const float*)d_in[21]; const float* bs2 = (const float*)d_in[22];
    float* out = (float*)d_out;

    float *qkv, *vt, *x2, *xn2, *eo, *shout, *gate, *bqkv, *wqkv3;
    int *eidx, *pos, *cnt;
    uint32_t *xn1h, *xn1l, *attnh, *attnl, *xn2h, *xn2l;
    uint32_t *disph, *displ, *hbh, *hbl, *shhh, *shhl;

    cudaGetSymbolAddress((void**)&qkv,  g_qkv);
    cudaGetSymbolAddress((void**)&vt,   g_vt);
    cudaGetSymbolAddress((void**)&x2,   g_x2);
    cudaGetSymbolAddress((void**)&xn2,  g_xn2);
    cudaGetSymbolAddress((void**)&eo,   g_eo);
    cudaGetSymbolAddress((void**)&shout,g_shout);
    cudaGetSymbolAddress((void**)&bqkv, g_bqkv);
    cudaGetSymbolAddress((void**)&wqkv3,g_wqkv3);
    cudaGetSymbolAddress((void**)&eidx, g_eidx);
    cudaGetSymbolAddress((void**)&pos,  g_pos);
    cudaGetSymbolAddress((void**)&cnt,  g_cnt);
    cudaGetSymbolAddress((void**)&gate, g_gate);
    cudaGetSymbolAddress((void**)&xn1h, g_xn1h);  cudaGetSymbolAddress((void**)&xn1l, g_xn1l);
    cudaGetSymbolAddress((void**)&attnh,g_attnh); cudaGetSymbolAddress((void**)&attnl,g_attnl);
    cudaGetSymbolAddress((void**)&xn2h, g_xn2h);  cudaGetSymbolAddress((void**)&xn2l, g_xn2l);
    cudaGetSymbolAddress((void**)&disph,g_disph); cudaGetSymbolAddress((void**)&displ,g_displ);
    cudaGetSymbolAddress((void**)&hbh,  g_hbh);   cudaGetSymbolAddress((void**)&hbl,  g_hbl);
    cudaGetSymbolAddress((void**)&shhh, g_shhh);  cudaGetSymbolAddress((void**)&shhl, g_shhl);

    cudaFuncSetAttribute(attn_mma,
                         cudaFuncAttributeMaxDynamicSharedMemorySize, ATT_SMEM);
    cudaFuncSetAttribute(tc_gemm<false, false, false>,
                         cudaFuncAttributeMaxDynamicSharedMemorySize, TC_SMEM);
    cudaFuncSetAttribute(tc_gemm<false, true, false>,
                         cudaFuncAttributeMaxDynamicSharedMemorySize, TC_SMEM);
    cudaFuncSetAttribute(tc_gemm<true, false, true>,
                         cudaFuncAttributeMaxDynamicSharedMemorySize, TC_SMEM);

    // 0) concat qkv weights (fp32) + biases
    wconcat3_kernel<<<dim3(D_ * D_ / 1024, 3), 256>>>(wq, wk, wv, wqkv3);
    concat3_kernel<<<dim3(D_/256, 3), 256>>>(bq, bk, bv, bqkv);

    // 1) LN1 -> split planes
    ln_kernel<false><<<T_, 256>>>(x, ln1g, ln1b, nullptr, xn1h, xn1l);

    // 2) fused QKV projection (B = raw fp32 weights, split in-kernel)
    tc_gemm<false, false, false><<<dim3(D_/128, T_/128, 3), 256, TC_SMEM>>>(
        xn1h, xn1l, wqkv3, bqkv, nullptr, qkv, nullptr, nullptr, nullptr,
        D_, D_, 0, (long)D_ * D_, D_, (long)T_ * D_);

    // 3) attention
    const float* q = qkv;
    const float* k = qkv + (long)T_ * D_;
    const float* v = qkv + 2L * T_ * D_;
    transpose_v<<<dim3(S_ / 32, 2, B_ * H_), 256>>>(v, vt);
    attn_mma<<<dim3(S_ / 128, H_, B_), 256, ATT_SMEM>>>(q, k, vt, mask, attnh, attnl);

    // 4) O projection + residual -> x2
    tc_gemm<false, true, false><<<dim3(D_/128, T_/128, 1), 256, TC_SMEM>>>(
        attnh, attnl, wo, bo, x, x2, nullptr, nullptr, nullptr,
        D_, D_, 0, 0, 0, 0);

    // 5) LN2
    ln_kernel<true><<<T_, 256>>>(x2, ln2g, ln2b, xn2, xn2h, xn2l);

    // 6) router + single-pass scan
    router_kernel<<<T_ / 8, 256>>>(xn2, wr, eidx, gate);
    scan_kernel<<<E_, 256>>>(eidx, pos, cnt);

    // 7) dispatch
    const int nz = E_ * CAP_ * D_ / 2 / 4;
    zero_kernel<<<(nz + 255) / 256, 256>>>((uint4*)disph, nz);
    zero_kernel<<<(nz + 255) / 256, 256>>>((uint4*)displ, nz);
    dispatch_kernel<<<KT_, 256>>>(xn2h, xn2l, eidx, pos, disph, displ);

    // 8) expert FFN (capacity-tile skip via cnt)
    tc_gemm<true, false, true><<<dim3(F_ / 128, CAP_ / 128, E_), 256, TC_SMEM>>>(
        disph, displ, w1, b1, nullptr, nullptr, hbh, hbl, cnt, D_, F_,
        (long)CAP_ * D_ / 2, (long)D_ * F_, (long)F_, (long)CAP_ * F_ / 2);
    tc_gemm<false, false, false><<<dim3(D_ / 128, CAP_ / 128, E_), 256, TC_SMEM>>>(
        hbh, hbl, w2, b2, nullptr, eo, nullptr, nullptr, cnt, F_, D_,
        (long)CAP_ * F_ / 2, (long)F_ * D_, (long)D_, (long)CAP_ * D_);

    // 9) shared expert
    tc_gemm<true, false, true><<<dim3(FS_ / 128, T_ / 128, 1), 256, TC_SMEM>>>(
        xn2h, xn2l, ws1, bs1, nullptr, nullptr, shhh, shhl, nullptr,
        D_, FS_, 0, 0, 0, 0);
    tc_gemm<false, false, false><<<dim3(D_ / 128, T_ / 128, 1), 256, TC_SMEM>>>(
        shhh, shhl, ws2, bs2, nullptr, shout, nullptr, nullptr, nullptr,
        FS_, D_, 0, 0, 0, 0);

    // 10) combine
    combine_kernel<<<T_, 256>>>(x2, shout, eo, eidx, pos, gate, out);
}

// round 13
// speedup vs baseline: 1.4282x; 1.4282x over previous
#include <cuda_runtime.h>
#include <cuda_bf16.h>
#include <math.h>
#include <stdint.h>

#define B_    4
#define S_    2048
#define D_    1024
#define H_    16
#define HD_   64
#define E_    8
#define F_    4096
#define FS_   2048
#define T_    8192
#define CAP_  2560
#define KT_   16384   // K * T slots

// ---------------- scratch (static device globals; no allocations) ----------
__device__ float g_qkv [3 * T_ * D_];     // q | k | v contiguous
__device__ float g_vt  [T_ * D_];
__device__ float g_x2  [T_ * D_];
__device__ float g_xn2 [T_ * D_];
__device__ float g_eo  [E_ * CAP_ * D_];
__device__ float g_shout[T_ * D_];
__device__ float g_bqkv[3 * D_];
__device__ float g_wqkv3[3 * D_ * D_];    // contiguous fp32 qkv weights
__device__ int   g_eidx[KT_];
__device__ int   g_pos [KT_];
__device__ int   g_cnt [E_];
__device__ float g_gate[KT_];
// bf16 hi/lo plane tensors: activations k-major [M][K/2] (u32 = bf16x2 k-pair)
__device__ uint32_t g_xn1h [T_ * D_ / 2],        g_xn1l [T_ * D_ / 2];
__device__ uint32_t g_attnh[T_ * D_ / 2],        g_attnl[T_ * D_ / 2];
__device__ uint32_t g_xn2h [T_ * D_ / 2],        g_xn2l [T_ * D_ / 2];
__device__ uint32_t g_disph[E_ * CAP_ * D_ / 2], g_displ[E_ * CAP_ * D_ / 2];
__device__ uint32_t g_hbh  [E_ * CAP_ * F_ / 2], g_hbl  [E_ * CAP_ * F_ / 2];
__device__ uint32_t g_shhh [T_ * FS_ / 2],       g_shhl [T_ * FS_ / 2];

// ---------------- helpers ---------------------------------------------------
__device__ __forceinline__ void split2(float x, float y,
                                       uint32_t& hi, uint32_t& lo)
{
    __nv_bfloat16 hx = __float2bfloat16(x);
    __nv_bfloat16 hy = __float2bfloat16(y);
    float rx = x - __bfloat162float(hx);
    float ry = y - __bfloat162float(hy);
    __nv_bfloat162 h2; h2.x = hx; h2.y = hy;
    __nv_bfloat162 l2; l2.x = __float2bfloat16(rx); l2.y = __float2bfloat16(ry);
    hi = *(uint32_t*)&h2;
    lo = *(uint32_t*)&l2;
}

__device__ __forceinline__ void mma16(float* acc,
                                      uint32_t a0, uint32_t a1, uint32_t a2, uint32_t a3,
                                      uint32_t b0, uint32_t b1)
{
    asm("mma.sync.aligned.m16n8k16.row.col.f32.bf16.bf16.f32 "
        "{%0,%1,%2,%3},{%4,%5,%6,%7},{%8,%9},{%0,%1,%2,%3};"
        : "+f"(acc[0]), "+f"(acc[1]), "+f"(acc[2]), "+f"(acc[3])
        : "r"(a0), "r"(a1), "r"(a2), "r"(a3), "r"(b0), "r"(b1));
}

__device__ __forceinline__ void ldsm4(uint32_t& r0, uint32_t& r1,
                                      uint32_t& r2, uint32_t& r3, uint32_t addr)
{
    asm volatile("ldmatrix.sync.aligned.m8n8.x4.shared.b16 {%0,%1,%2,%3}, [%4];"
                 : "=r"(r0), "=r"(r1), "=r"(r2), "=r"(r3) : "r"(addr));
}

__device__ __forceinline__ void cpasync16(uint32_t dst, const void* src)
{
    asm volatile("cp.async.cg.shared.global [%0], [%1], 16;"
                 :: "r"(dst), "l"(src));
}
#define CP_COMMIT() asm volatile("cp.async.commit_group;" ::: "memory")
#define CP_WAIT0()  asm volatile("cp.async.wait_group 0;" ::: "memory")

// ---------------- QKV weight/bias concat ------------------------------------
__global__ void __launch_bounds__(256) wconcat3_kernel(
    const float* __restrict__ a, const float* __restrict__ b,
    const float* __restrict__ c, float* __restrict__ out)
{
    const long i = (long)blockIdx.x * 1024 + threadIdx.x * 4;
    const float* src = blockIdx.y == 0 ? a : (blockIdx.y == 1 ? b : c);
    *(float4*)&out[(long)blockIdx.y * D_ * D_ + i] = *(const float4*)&src[i];
}
__global__ void __launch_bounds__(256) concat3_kernel(
    const float* __restrict__ a, const float* __restrict__ b,
    const float* __restrict__ c, float* __restrict__ out)
{
    const int i = blockIdx.x * 256 + threadIdx.x;
    const float* src = blockIdx.y == 0 ? a : (blockIdx.y == 1 ? b : c);
    out[blockIdx.y * D_ + i] = src[i];
}

// ---------------- bf16x3 tensor-core GEMM ----------------------------------
// CTA 128x128, warp tile 64x32, BK=32 (16 k-pairs), 2-stage, 1 barrier/iter.
// A: pre-split bf16 planes [M][K/2] via cp.async, ldmatrix fragments
//    (pitch 20, conflict-free).
// B: raw fp32 [K][N] split in-kernel -> k-major smem planes [kp][n] pitch 136,
//    STS.128 at lane*16B (conflict-free), scalar-LDS B fragments (round-9
//    proven layout).
#define APW  20
#define BPW  136
#define AWu  (128 * APW)           // 2560 u32 per A plane
#define BWu  (16 * BPW)            // 2176 u32 per B plane
#define STW  (2 * AWu + 2 * BWu)   // 9472 u32 / stage
#define TC_SMEM (2 * STW * 4)      // 75776 B

#define OF_AH 0
#define OF_AL AWu
#define OF_BH (2 * AWu)
#define OF_BL (2 * AWu + BWu)

__device__ __forceinline__ void fillA(
    uint32_t sb, const uint32_t* __restrict__ Ah, const uint32_t* __restrict__ Al,
    int kt, int K2, int m0, int tid)
{
    #pragma unroll
    for (int i = 0; i < 2; i++) {
        const int lin = i * 256 + tid;
        const int row = lin >> 2, ch = (lin & 3) * 4;
        const long src = (long)(m0 + row) * K2 + kt * 16 + ch;
        const uint32_t d = sb + (uint32_t)(row * APW + ch) * 4;
        cpasync16(d + OF_AH * 4, Ah + src);
        cpasync16(d + OF_AL * 4, Al + src);
    }
}

// load B tile (32 k x 128 n) for tile kt into registers (coalesced LDG.128)
__device__ __forceinline__ void loadB(
    const float* __restrict__ Bw, int kt, int N, int n0, int tid,
    float4 r0[2], float4 r1[2])
{
    const int kp = tid >> 5;             // 0..7
    const int n4 = (tid & 31) * 4;
    #pragma unroll
    for (int i = 0; i < 2; i++) {
        const long k0 = (long)(kt * 32 + 2 * (kp + i * 8));
        r0[i] = *(const float4*)(Bw + k0 * N + n0 + n4);
        r1[i] = *(const float4*)(Bw + (k0 + 1) * N + n0 + n4);
    }
}

// split + STS.128 into k-major smem planes (conflict-free: lane*16B)
__device__ __forceinline__ void stsB(uint32_t sb, int tid,
                                     const float4 r0[2], const float4 r1[2])
{
    const int kp = tid >> 5;
    const int n4 = (tid & 31) * 4;
    #pragma unroll
    for (int i = 0; i < 2; i++) {
        const int kpi = kp + i * 8;
        uint32_t h[4], l[4];
        split2(r0[i].x, r1[i].x, h[0], l[0]);
        split2(r0[i].y, r1[i].y, h[1], l[1]);
        split2(r0[i].z, r1[i].z, h[2], l[2]);
        split2(r0[i].w, r1[i].w, h[3], l[3]);
        const uint32_t off = sb + (uint32_t)(kpi * BPW + n4) * 4;
        asm volatile("st.shared.v4.b32 [%0], {%1,%2,%3,%4};"
            :: "r"(off + OF_BH * 4), "r"(h[0]), "r"(h[1]), "r"(h[2]), "r"(h[3]));
        asm volatile("st.shared.v4.b32 [%0], {%1,%2,%3,%4};"
            :: "r"(off + OF_BL * 4), "r"(l[0]), "r"(l[1]), "r"(l[2]), "r"(l[3]));
    }
}

__device__ __forceinline__ void kslice_mma(
    const uint32_t* __restrict__ buf, uint32_t sb, int kp0,
    int wm, int wn, int g, int t, uint32_t a_lo, float acc[4][4][4])
{
    const uint32_t* Bh = buf + OF_BH;
    const uint32_t* Bl = buf + OF_BL;

    uint32_t bh[4][2], bl[4][2];
    #pragma unroll
    for (int nt = 0; nt < 4; nt++) {
        const int col = wn * 32 + nt * 8 + g;
        bh[nt][0] = Bh[(kp0 + t)     * BPW + col];
        bh[nt][1] = Bh[(kp0 + t + 4) * BPW + col];
        bl[nt][0] = Bl[(kp0 + t)     * BPW + col];
        bl[nt][1] = Bl[(kp0 + t + 4) * BPW + col];
    }
    #pragma unroll
    for (int mt = 0; mt < 4; mt++) {
        const uint32_t abase = sb + (uint32_t)(((wm * 64 + mt * 16) * APW + kp0) * 4) + a_lo;
        uint32_t ah0, ah1, ah2, ah3, al0, al1, al2, al3;
        ldsm4(ah0, ah1, ah2, ah3, abase + OF_AH * 4);
        ldsm4(al0, al1, al2, al3, abase + OF_AL * 4);
        #pragma unroll
        for (int nt = 0; nt < 4; nt++)
            mma16(acc[mt][nt], ah0, ah1, ah2, ah3, bh[nt][0], bh[nt][1]);
        #pragma unroll
        for (int nt = 0; nt < 4; nt++)
            mma16(acc[mt][nt], ah0, ah1, ah2, ah3, bl[nt][0], bl[nt][1]);
        #pragma unroll
        for (int nt = 0; nt < 4; nt++)
            mma16(acc[mt][nt], al0, al1, al2, al3, bh[nt][0], bh[nt][1]);
    }
}

template<bool GELU, bool RES, bool SPLITOUT>
__global__ void __launch_bounds__(256, 2) tc_gemm(
    const uint32_t* __restrict__ Ah, const uint32_t* __restrict__ Al,
    const float* __restrict__ Bw,
    const float* __restrict__ bias, const float* __restrict__ res,
    float* __restrict__ C, uint32_t* __restrict__ Ch, uint32_t* __restrict__ Cl,
    const int* __restrict__ rowcnt,
    int Kd, int N, long sA, long sB, long sBias, long sC)
{
    extern __shared__ uint32_t smw[];
    const uint32_t sbase = (uint32_t)__cvta_generic_to_shared(smw);
    const int tid = threadIdx.x, wid = tid >> 5, lane = tid & 31;
    const int g = lane >> 2, t = lane & 3;
    const int wm = wid & 1, wn = wid >> 1;
    const int bz = blockIdx.z;
    const int m0 = blockIdx.y * 128, n0 = blockIdx.x * 128;
    if (rowcnt != nullptr && m0 >= __ldg(&rowcnt[bz])) return;

    Ah += bz * sA; Al += bz * sA;
    Bw += bz * sB;
    bias += bz * sBias;
    if (SPLITOUT) { Ch += bz * sC; Cl += bz * sC; }
    else          { C  += bz * sC; }
    const int K2 = Kd >> 1;
    const int NT = Kd >> 5;

    const uint32_t a_lo = (uint32_t)(((lane & 15) * APW + ((lane >> 4) << 2)) * 4);

    float acc[4][4][4];
    #pragma unroll
    for (int mt = 0; mt < 4; mt++)
        #pragma unroll
        for (int nt = 0; nt < 4; nt++)
            #pragma unroll
            for (int c = 0; c < 4; c++) acc[mt][nt][c] = 0.0f;

    float4 br0[2], br1[2];
    fillA(sbase, Ah, Al, 0, K2, m0, tid);
    CP_COMMIT();
    loadB(Bw, 0, N, n0, tid, br0, br1);
    stsB(sbase, tid, br0, br1);

    int st = 0;
    for (int kt = 0; kt < NT; kt++) {
        CP_WAIT0();
        __syncthreads();
        if (kt + 1 < NT) {
            fillA(sbase + (st ^ 1) * (STW * 4), Ah, Al, kt + 1, K2, m0, tid);
            loadB(Bw, kt + 1, N, n0, tid, br0, br1);
        }
        CP_COMMIT();
        const uint32_t* buf = smw + st * STW;
        const uint32_t sb = sbase + st * (STW * 4);
        kslice_mma(buf, sb, 0, wm, wn, g, t, a_lo, acc);
        kslice_mma(buf, sb, 8, wm, wn, g, t, a_lo, acc);
        if (kt + 1 < NT)
            stsB(sbase + (st ^ 1) * (STW * 4), tid, br0, br1);
        st ^= 1;
    }

    // ---- epilogue ----
    #pragma unroll
    for (int mt = 0; mt < 4; mt++) {
        const int row = m0 + wm * 64 + mt * 16 + g;
        #pragma unroll
        for (int nt = 0; nt < 4; nt++) {
            const int col = n0 + wn * 32 + nt * 8 + t * 2;
            const float b0v = bias[col], b1v = bias[col + 1];
            float v0 = acc[mt][nt][0] + b0v;
            float v1 = acc[mt][nt][1] + b1v;
            float v2 = acc[mt][nt][2] + b0v;
            float v3 = acc[mt][nt][3] + b1v;
            if (GELU) {
                v0 *= normcdff(v0); v1 *= normcdff(v1);
                v2 *= normcdff(v2); v3 *= normcdff(v3);
            }
            if (SPLITOUT) {
                uint32_t h0, l0, h1, l1;
                split2(v0, v1, h0, l0);
                split2(v2, v3, h1, l1);
                const long p0 = (long)row * (N >> 1) + (col >> 1);
                const long p1 = (long)(row + 8) * (N >> 1) + (col >> 1);
                Ch[p0] = h0; Cl[p0] = l0;
                Ch[p1] = h1; Cl[p1] = l1;
            } else {
                const long o0 = (long)row * N + col;
                const long o1 = (long)(row + 8) * N + col;
                if (RES) {
                    const float2 r0 = *(const float2*)&res[o0];
                    const float2 r1 = *(const float2*)&res[o1];
                    v0 += r0.x; v1 += r0.y; v2 += r1.x; v3 += r1.y;
                }
                float2 w0; w0.x = v0; w0.y = v1;
                float2 w1; w1.x = v2; w1.y = v3;
                *(float2*)&C[o0] = w0;
                *(float2*)&C[o1] = w1;
            }
        }
    }
}

// ---------------- V transpose ----------------------------------------------
__global__ void __launch_bounds__(256) transpose_v(const float* __restrict__ v,
                                                   float* __restrict__ vt)
{
    __shared__ float tile[32][33];
    const int bh = blockIdx.z;
    const int b = bh >> 4, h = bh & 15;
    const int s0 = blockIdx.x * 32, d0 = blockIdx.y * 32;
    const int tx = threadIdx.x & 31, ty = threadIdx.x >> 5;
    #pragma unroll
    for (int i = 0; i < 32; i += 8)
        tile[ty + i][tx] = v[(long)(b * S_ + s0 + ty + i) * D_ + h * 64 + d0 + tx];
    __syncthreads();
    #pragma unroll
    for (int i = 0; i < 32; i += 8)
        vt[((long)bh * 64 + d0 + ty + i) * S_ + s0 + tx] = tile[tx][ty + i];
}

// ---------------- Flash attention, bf16x3 tensor cores ---------------------
#define QP 72
#define SM_QH 0
#define SM_QL (128 * QP)
#define SM_KH (2 * 128 * QP)
#define SM_KL (SM_KH + 64 * QP)
#define SM_VH (SM_KL + 64 * QP)
#define SM_VL (SM_VH + 64 * QP)
#define SM_END (SM_VL + 64 * QP)
#define ATT_SMEM (SM_END * 2 + 128)

__global__ void __launch_bounds__(256) attn_mma(
    const float* __restrict__ qg, const float* __restrict__ kg,
    const float* __restrict__ vtg, const unsigned char* __restrict__ maskg,
    uint32_t* __restrict__ oh, uint32_t* __restrict__ ol)
{
    extern __shared__ uint16_t sm16[];
    char* ms = (char*)(sm16 + SM_END);

    const int b = blockIdx.z, h = blockIdx.y, q0 = blockIdx.x * 128;
    const int tid = threadIdx.x, wq = tid >> 5, lane = tid & 31;
    const int g = lane >> 2, t4 = lane & 3;
    const float NEG = -3.402823466e38f;

    #pragma unroll
    for (int i = 0; i < 8; i++) {
        const int lin = i * 256 + tid;
        const int row = lin >> 4, c4 = (lin & 15) * 4;
        const float4 v = *(const float4*)&qg[(long)(b * S_ + q0 + row) * D_ + h * 64 + c4];
        uint32_t h0, l0, h1, l1;
        split2(v.x, v.y, h0, l0);
        split2(v.z, v.w, h1, l1);
        uint2 hv; hv.x = h0; hv.y = h1;
        uint2 lv; lv.x = l0; lv.y = l1;
        *(uint2*)&sm16[SM_QH + row * QP + c4] = hv;
        *(uint2*)&sm16[SM_QL + row * QP + c4] = lv;
    }
    __syncthreads();

    uint32_t qfh[4][4], qfl[4][4];
    {
        const int qr = wq * 16 + g;
        #pragma unroll
        for (int ks = 0; ks < 4; ks++) {
            const int kc = ks * 16 + 2 * t4;
            qfh[ks][0] = *(const uint32_t*)&sm16[SM_QH + qr * QP + kc];
            qfh[ks][1] = *(const uint32_t*)&sm16[SM_QH + (qr + 8) * QP + kc];
            qfh[ks][2] = *(const uint32_t*)&sm16[SM_QH + qr * QP + kc + 8];
            qfh[ks][3] = *(const uint32_t*)&sm16[SM_QH + (qr + 8) * QP + kc + 8];
            qfl[ks][0] = *(const uint32_t*)&sm16[SM_QL + qr * QP + kc];
            qfl[ks][1] = *(const uint32_t*)&sm16[SM_QL + (qr + 8) * QP + kc];
            qfl[ks][2] = *(const uint32_t*)&sm16[SM_QL + qr * QP + kc + 8];
            qfl[ks][3] = *(const uint32_t*)&sm16[SM_QL + (qr + 8) * QP + kc + 8];
        }
    }

    float m[2], l[2], oacc[8][4];
    m[0] = m[1] = NEG; l[0] = l[1] = 0.0f;
    #pragma unroll
    for (int j = 0; j < 8; j++)
        #pragma unroll
        for (int c = 0; c < 4; c++) oacc[j][c] = 0.0f;

    for (int kt = 0; kt < 32; kt++) {
        const int k0 = kt * 64;
        __syncthreads();
        #pragma unroll
        for (int i = 0; i < 4; i++) {
            const int lin = i * 256 + tid;
            const int row = lin >> 4, c4 = (lin & 15) * 4;
            const float4 kv = *(const float4*)&kg[(long)(b * S_ + k0 + row) * D_ + h * 64 + c4];
            const float4 vv = *(const float4*)&vtg[((long)(b * 16 + h) * 64 + row) * S_ + k0 + c4];
            uint32_t h0, l0, h1, l1;
            split2(kv.x, kv.y, h0, l0);
            split2(kv.z, kv.w, h1, l1);
            uint2 a; a.x = h0; a.y = h1;
            uint2 c; c.x = l0; c.y = l1;
            *(uint2*)&sm16[SM_KH + row * QP + c4] = a;
            *(uint2*)&sm16[SM_KL + row * QP + c4] = c;
            split2(vv.x, vv.y, h0, l0);
            split2(vv.z, vv.w, h1, l1);
            a.x = h0; a.y = h1;
            c.x = l0; c.y = l1;
            *(uint2*)&sm16[SM_VH + row * QP + c4] = a;
            *(uint2*)&sm16[SM_VL + row * QP + c4] = c;
        }
        if (tid < 64) ms[tid] = (char)maskg[b * S_ + k0 + tid];
        __syncthreads();

        float sacc[8][4];
        #pragma unroll
        for (int j = 0; j < 8; j++)
            #pragma unroll
            for (int c = 0; c < 4; c++) sacc[j][c] = 0.0f;

        #pragma unroll
        for (int ks = 0; ks < 4; ks++) {
            const int kc = ks * 16 + 2 * t4;
            uint32_t kbh[8][2], kbl[8][2];
            #pragma unroll
            for (int j = 0; j < 8; j++) {
                const int krow = (8 * j + g) * QP;
                kbh[j][0] = *(const uint32_t*)&sm16[SM_KH + krow + kc];
                kbh[j][1] = *(const uint32_t*)&sm16[SM_KH + krow + kc + 8];
                kbl[j][0] = *(const uint32_t*)&sm16[SM_KL + krow + kc];
                kbl[j][1] = *(const uint32_t*)&sm16[SM_KL + krow + kc + 8];
            }
            #pragma unroll
            for (int j = 0; j < 8; j++)
                mma16(sacc[j], qfh[ks][0], qfh[ks][1], qfh[ks][2], qfh[ks][3],
                      kbh[j][0], kbh[j][1]);
            #pragma unroll
            for (int j = 0; j < 8; j++)
                mma16(sacc[j], qfh[ks][0], qfh[ks][1], qfh[ks][2], qfh[ks][3],
                      kbl[j][0], kbl[j][1]);
            #pragma unroll
            for (int j = 0; j < 8; j++)
                mma16(sacc[j], qfl[ks][0], qfl[ks][1], qfl[ks][2], qfl[ks][3],
                      kbh[j][0], kbh[j][1]);
        }

        #pragma unroll
        for (int j = 0; j < 8; j++) {
            const int col = 8 * j + 2 * t4;
            const bool m0k = ms[col] != 0;
            const bool m1k = ms[col + 1] != 0;
            sacc[j][0] = m0k ? NEG : sacc[j][0] * 0.125f;
            sacc[j][1] = m1k ? NEG : sacc[j][1] * 0.125f;
            sacc[j][2] = m0k ? NEG : sacc[j][2] * 0.125f;
            sacc[j][3] = m1k ? NEG : sacc[j][3] * 0.125f;
        }

        #pragma unroll
        for (int r = 0; r < 2; r++) {
            float rmax = NEG;
            #pragma unroll
            for (int j = 0; j < 8; j++) {
                rmax = fmaxf(rmax, sacc[j][2 * r]);
                rmax = fmaxf(rmax, sacc[j][2 * r + 1]);
            }
            rmax = fmaxf(rmax, __shfl_xor_sync(0xffffffffu, rmax, 1));
            rmax = fmaxf(rmax, __shfl_xor_sync(0xffffffffu, rmax, 2));
            const float mnew = fmaxf(m[r], rmax);
            const float corr = expf(m[r] - mnew);
            float rsum = 0.0f;
            #pragma unroll
            for (int j = 0; j < 8; j++) {
                float p0 = expf(sacc[j][2 * r]     - mnew);
                float p1 = expf(sacc[j][2 * r + 1] - mnew);
                sacc[j][2 * r] = p0; sacc[j][2 * r + 1] = p1;
                rsum += p0 + p1;
            }
            rsum += __shfl_xor_sync(0xffffffffu, rsum, 1);
            rsum += __shfl_xor_sync(0xffffffffu, rsum, 2);
            l[r] = l[r] * corr + rsum;
            m[r] = mnew;
            #pragma unroll
            for (int j = 0; j < 8; j++) {
                oacc[j][2 * r]     *= corr;
                oacc[j][2 * r + 1] *= corr;
            }
        }

        #pragma unroll
        for (int ks = 0; ks < 4; ks++) {
            const int j0 = 2 * ks, j1 = 2 * ks + 1;
            uint32_t ph0, pl0, ph1, pl1, ph2, pl2, ph3, pl3;
            split2(sacc[j0][0], sacc[j0][1], ph0, pl0);
            split2(sacc[j0][2], sacc[j0][3], ph1, pl1);
            split2(sacc[j1][0], sacc[j1][1], ph2, pl2);
            split2(sacc[j1][2], sacc[j1][3], ph3, pl3);
            const int kc = ks * 16 + 2 * t4;
            uint32_t vfh[8][2], vfl[8][2];
            #pragma unroll
            for (int j = 0; j < 8; j++) {
                const int vrow = (8 * j + g) * QP;
                vfh[j][0] = *(const uint32_t*)&sm16[SM_VH + vrow + kc];
                vfh[j][1] = *(const uint32_t*)&sm16[SM_VH + vrow + kc + 8];
                vfl[j][0] = *(const uint32_t*)&sm16[SM_VL + vrow + kc];
                vfl[j][1] = *(const uint32_t*)&sm16[SM_VL + vrow + kc + 8];
            }
            #pragma unroll
            for (int j = 0; j < 8; j++)
                mma16(oacc[j], ph0, ph1, ph2, ph3, vfh[j][0], vfh[j][1]);
            #pragma unroll
            for (int j = 0; j < 8; j++)
                mma16(oacc[j], ph0, ph1, ph2, ph3, vfl[j][0], vfl[j][1]);
            #pragma unroll
            for (int j = 0; j < 8; j++)
                mma16(oacc[j], pl0, pl1, pl2, pl3, vfh[j][0], vfh[j][1]);
        }
    }

    const float inv0 = 1.0f / l[0], inv1 = 1.0f / l[1];
    const int row0 = q0 + wq * 16 + g;
    #pragma unroll
    for (int j = 0; j < 8; j++) {
        const int col = h * 64 + 8 * j + 2 * t4;
        uint32_t h0, l0, h1, l1;
        split2(oacc[j][0] * inv0, oacc[j][1] * inv0, h0, l0);
        split2(oacc[j][2] * inv1, oacc[j][3] * inv1, h1, l1);
        const long p0 = (long)(b * S_ + row0) * (D_ / 2) + (col >> 1);
        const long p1 = (long)(b * S_ + row0 + 8) * (D_ / 2) + (col >> 1);
        oh[p0] = h0; ol[p0] = l0;
        oh[p1] = h1; ol[p1] = l1;
    }
}

// ---------------- LayerNorm (writes split planes; optional fp32) -----------
template<bool F32OUT>
__global__ void __launch_bounds__(256) ln_kernel(const float* __restrict__ x,
                                                 const float* __restrict__ g,
                                                 const float* __restrict__ b,
                                                 float* __restrict__ outf,
                                                 uint32_t* __restrict__ outh,
                                                 uint32_t* __restrict__ outl)
{
    const int row = blockIdx.x;
    const int tid = threadIdx.x;
    const float4 v = ((const float4*)(x + (long)row * D_))[tid];

    __shared__ float red[256];
    __shared__ float s_mu, s_rstd;

    float s = v.x + v.y + v.z + v.w;
    red[tid] = s; __syncthreads();
    for (int o = 128; o > 0; o >>= 1) {
        if (tid < o) red[tid] += red[tid + o];
        __syncthreads();
    }
    if (tid == 0) s_mu = red[0] * (1.0f / D_);
    __syncthreads();
    const float mu = s_mu;

    float dx0 = v.x - mu, dx1 = v.y - mu, dx2 = v.z - mu, dx3 = v.w - mu;
    float sq = dx0*dx0 + dx1*dx1 + dx2*dx2 + dx3*dx3;
    red[tid] = sq; __syncthreads();
    for (int o = 128; o > 0; o >>= 1) {
        if (tid < o) red[tid] += red[tid + o];
        __syncthreads();
    }
    if (tid == 0) s_rstd = rsqrtf(red[0] * (1.0f / D_) + 1e-5f);
    __syncthreads();
    const float rstd = s_rstd;

    const float4 gg = ((const float4*)g)[tid];
    const float4 bb = ((const float4*)b)[tid];
    float4 o4;
    o4.x = dx0 * rstd * gg.x + bb.x;
    o4.y = dx1 * rstd * gg.y + bb.y;
    o4.z = dx2 * rstd * gg.z + bb.z;
    o4.w = dx3 * rstd * gg.w + bb.w;
    if (F32OUT)
        ((float4*)(outf + (long)row * D_))[tid] = o4;
    uint32_t h0, l0, h1, l1;
    split2(o4.x, o4.y, h0, l0);
    split2(o4.z, o4.w, h1, l1);
    uint2 hv; hv.x = h0; hv.y = h1;
    uint2 lv; lv.x = l0; lv.y = l1;
    *(uint2*)&outh[(long)row * (D_ / 2) + tid * 2] = hv;
    *(uint2*)&outl[(long)row * (D_ / 2) + tid * 2] = lv;
}

// ---------------- Router --------------------------------------------------
__global__ void __launch_bounds__(256) router_kernel(
    const float* __restrict__ xn, const float* __restrict__ wr,
    int* __restrict__ eidx, float* __restrict__ gate)
{
    const int warp = threadIdx.x >> 5, lane = threadIdx.x & 31;
    const int t = blockIdx.x * 8 + warp;
    const float* xr = xn + (long)t * D_;

    float a[E_];
    #pragma unroll
    for (int e = 0; e < E_; e++) a[e] = 0.0f;
    for (int d = lane; d < D_; d += 32) {
        const float xv = xr[d];
        const float* w = wr + d * E_;
        #pragma unroll
        for (int e = 0; e < E_; e++) a[e] += xv * w[e];
    }
    #pragma unroll
    for (int e = 0; e < E_; e++)
        #pragma unroll
        for (int o = 16; o > 0; o >>= 1)
            a[e] += __shfl_xor_sync(0xffffffffu, a[e], o);

    if (lane == 0) {
        float mx = a[0];
        #pragma unroll
        for (int e = 1; e < E_; e++) mx = fmaxf(mx, a[e]);
        float ex[E_];
        #pragma unroll
        for (int e = 0; e < E_; e++) ex[e] = expf(a[e] - mx);
        int i0 = 0; float v0 = ex[0];
        #pragma unroll
        for (int e = 1; e < E_; e++) if (ex[e] > v0) { v0 = ex[e]; i0 = e; }
        int i1 = -1; float v1 = -1.0f;
        #pragma unroll
        for (int e = 0; e < E_; e++)
            if (e != i0 && ex[e] > v1) { v1 = ex[e]; i1 = e; }
        const float inv = 1.0f / (v0 + v1);
        eidx[t]       = i0; gate[t]       = v0 * inv;
        eidx[T_ + t]  = i1; gate[T_ + t]  = v1 * inv;
    }
}

// ---------------- Single-pass slot-major capacity scan ---------------------
__global__ void __launch_bounds__(256) scan_kernel(const int* __restrict__ eidx,
                                                   int* __restrict__ pos,
                                                   int* __restrict__ cnt)
{
    const int e = blockIdx.x;
    const int tid = threadIdx.x;
    const int base = tid * 64;

    int lc = 0;
    #pragma unroll 8
    for (int j = 0; j < 64; j++)
        lc += (eidx[base + j] == e) ? 1 : 0;

    __shared__ int sd[256];
    sd[tid] = lc;
    __syncthreads();
    for (int o = 1; o < 256; o <<= 1) {
        int v = (tid >= o) ? sd[tid - o] : 0;
        __syncthreads();
        sd[tid] += v;
        __syncthreads();
    }
    int run = sd[tid] - lc;
    #pragma unroll 8
    for (int j = 0; j < 64; j++) {
        if (eidx[base + j] == e) pos[base + j] = run++;
    }
    if (tid == 255) cnt[e] = sd[255] < CAP_ ? sd[255] : CAP_;
}

__global__ void __launch_bounds__(256) dispatch_kernel(
    const uint32_t* __restrict__ xnh, const uint32_t* __restrict__ xnl,
    const int* __restrict__ eidx, const int* __restrict__ pos,
    uint32_t* __restrict__ dh, uint32_t* __restrict__ dl)
{
    const int s = blockIdx.x;
    const int p = pos[s];
    if (p >= CAP_) return;
    const int e = eidx[s];
    const int t = s & (T_ - 1);
    const long src = (long)t * (D_ / 2);
    const long dst = ((long)e * CAP_ + p) * (D_ / 2);
    const uint2* sh = (const uint2*)(xnh + src);
    const uint2* sl = (const uint2*)(xnl + src);
    uint2* th = (uint2*)(dh + dst);
    uint2* tl = (uint2*)(dl + dst);
    th[threadIdx.x] = sh[threadIdx.x];
    tl[threadIdx.x] = sl[threadIdx.x];
}

__global__ void __launch_bounds__(256) combine_kernel(
    const float* __restrict__ x2, const float* __restrict__ shout,
    const float* __restrict__ eo, const int* __restrict__ eidx,
    const int* __restrict__ pos, const float* __restrict__ gate,
    float* __restrict__ out)
{
    const int t = blockIdx.x;
    const int p0 = pos[t], p1 = pos[T_ + t];
    const float g0 = gate[t]      * (p0 < CAP_ ? 1.0f : 0.0f);
    const float g1 = gate[T_ + t] * (p1 < CAP_ ? 1.0f : 0.0f);
    const long o0 = ((long)eidx[t]      * CAP_ + min(p0, CAP_ - 1)) * D_;
    const long o1 = ((long)eidx[T_ + t] * CAP_ + min(p1, CAP_ - 1)) * D_;

    const int c = threadIdx.x;
    float4 a = ((const float4*)(x2 + (long)t * D_))[c];
    float4 s = ((const float4*)(shout + (long)t * D_))[c];
    float4 r0 = ((const float4*)(eo + o0))[c];
    float4 r1 = ((const float4*)(eo + o1))[c];
    float4 o;
    o.x = a.x + s.x + g0 * r0.x + g1 * r1.x;
    o.y = a.y + s.y + g0 * r0.y + g1 * r1.y;
    o.z = a.z + s.z + g0 * r0.z + g1 * r1.z;
    o.w = a.w + s.w + g0 * r0.w + g1 * r1.w;
    ((float4*)(out + (long)t * D_))[c] = o;
}

// ---------------------------------------------------------------------------
extern "C" void kernel_launch(void* const* d_in, const int* in_sizes, int n_in,
                              void* d_out, int out_size)
{
    const float* x   = (const float*)d_in[0];
    const unsigned char* mask = (const unsigned char*)d_in[1];
    const float* ln1g = (const float*)d_in[2];
    const float* ln1b = (const float*)d_in[3];
    const float* wq = (const float*)d_in[4];  const float* bq = (const float*)d_in[5];
    const float* wk = (const float*)d_in[6];  const float* bk = (const float*)d_in[7];
    const float* wv = (const float*)d_in[8];  const float* bv = (const float*)d_in[9];
    const float* wo = (const float*)d_in[10]; const float* bo = (const float*)d_in[11];
    const float* ln2g = (const float*)d_in[12];
    const float* ln2b = (const float*)d_in[13];
    const float* wr = (const float*)d_in[14];
    const float* w1 = (const float*)d_in[15]; const float* b1 = (const float*)d_in[16];
    const float* w2 = (const float*)d_in[17]; const float* b2 = (const float*)d_in[18];
    const float* ws1 = (const float*)d_in[19]; const float* bs1 = (const float*)d_in[20];
    const float* ws2 = (const float*)d_in[21]; const float* bs2 = (const float*)d_in[22];
    float* out = (float*)d_out;

    float *qkv, *vt, *x2, *xn2, *eo, *shout, *gate, *bqkv, *wqkv3;
    int *eidx, *pos, *cnt;
    uint32_t *xn1h, *xn1l, *attnh, *attnl, *xn2h, *xn2l;
    uint32_t *disph, *displ, *hbh, *hbl, *shhh, *shhl;

    cudaGetSymbolAddress((void**)&qkv,  g_qkv);
    cudaGetSymbolAddress((void**)&vt,   g_vt);
    cudaGetSymbolAddress((void**)&x2,   g_x2);
    cudaGetSymbolAddress((void**)&xn2,  g_xn2);
    cudaGetSymbolAddress((void**)&eo,   g_eo);
    cudaGetSymbolAddress((void**)&shout,g_shout);
    cudaGetSymbolAddress((void**)&bqkv, g_bqkv);
    cudaGetSymbolAddress((void**)&wqkv3,g_wqkv3);
    cudaGetSymbolAddress((void**)&eidx, g_eidx);
    cudaGetSymbolAddress((void**)&pos,  g_pos);
    cudaGetSymbolAddress((void**)&cnt,  g_cnt);
    cudaGetSymbolAddress((void**)&gate, g_gate);
    cudaGetSymbolAddress((void**)&xn1h, g_xn1h);  cudaGetSymbolAddress((void**)&xn1l, g_xn1l);
    cudaGetSymbolAddress((void**)&attnh,g_attnh); cudaGetSymbolAddress((void**)&attnl,g_attnl);
    cudaGetSymbolAddress((void**)&xn2h, g_xn2h);  cudaGetSymbolAddress((void**)&xn2l, g_xn2l);
    cudaGetSymbolAddress((void**)&disph,g_disph); cudaGetSymbolAddress((void**)&displ,g_displ);
    cudaGetSymbolAddress((void**)&hbh,  g_hbh);   cudaGetSymbolAddress((void**)&hbl,  g_hbl);
    cudaGetSymbolAddress((void**)&shhh, g_shhh);  cudaGetSymbolAddress((void**)&shhl, g_shhl);

    cudaFuncSetAttribute(attn_mma,
                         cudaFuncAttributeMaxDynamicSharedMemorySize, ATT_SMEM);
    cudaFuncSetAttribute(tc_gemm<false, false, false>,
                         cudaFuncAttributeMaxDynamicSharedMemorySize, TC_SMEM);
    cudaFuncSetAttribute(tc_gemm<false, true, false>,
                         cudaFuncAttributeMaxDynamicSharedMemorySize, TC_SMEM);
    cudaFuncSetAttribute(tc_gemm<true, false, true>,
                         cudaFuncAttributeMaxDynamicSharedMemorySize, TC_SMEM);

    // 0) concat qkv weights (fp32) + biases (replaces all weight pre-splitting)
    wconcat3_kernel<<<dim3(D_ * D_ / 1024, 3), 256>>>(wq, wk, wv, wqkv3);
    concat3_kernel<<<dim3(D_/256, 3), 256>>>(bq, bk, bv, bqkv);

    // 1) LN1 -> split planes
    ln_kernel<false><<<T_, 256>>>(x, ln1g, ln1b, nullptr, xn1h, xn1l);

    // 2) fused QKV projection (B = raw fp32 weights, split in-kernel)
    tc_gemm<false, false, false><<<dim3(D_/128, T_/128, 3), 256, TC_SMEM>>>(
        xn1h, xn1l, wqkv3, bqkv, nullptr, qkv, nullptr, nullptr, nullptr,
        D_, D_, 0, (long)D_ * D_, D_, (long)T_ * D_);

    // 3) attention
    const float* q = qkv;
    const float* k = qkv + (long)T_ * D_;
    const float* v = qkv + 2L * T_ * D_;
    transpose_v<<<dim3(S_ / 32, 2, B_ * H_), 256>>>(v, vt);
    attn_mma<<<dim3(S_ / 128, H_, B_), 256, ATT_SMEM>>>(q, k, vt, mask, attnh, attnl);

    // 4) O projection + residual -> x2
    tc_gemm<false, true, false><<<dim3(D_/128, T_/128, 1), 256, TC_SMEM>>>(
        attnh, attnl, wo, bo, x, x2, nullptr, nullptr, nullptr,
        D_, D_, 0, 0, 0, 0);

    // 5) LN2
    ln_kernel<true><<<T_, 256>>>(x2, ln2g, ln2b, xn2, xn2h, xn2l);

    // 6) router + single-pass scan
    router_kernel<<<T_ / 8, 256>>>(xn2, wr, eidx, gate);
    scan_kernel<<<E_, 256>>>(eidx, pos, cnt);

    // 7) dispatch (no zeroing: rows >= cnt only feed outputs combine never reads)
    dispatch_kernel<<<KT_, 256>>>(xn2h, xn2l, eidx, pos, disph, displ);

    // 8) expert FFN (capacity-tile skip via cnt)
    tc_gemm<true, false, true><<<dim3(F_ / 128, CAP_ / 128, E_), 256, TC_SMEM>>>(
        disph, displ, w1, b1, nullptr, nullptr, hbh, hbl, cnt, D_, F_,
        (long)CAP_ * D_ / 2, (long)D_ * F_, (long)F_, (long)CAP_ * F_ / 2);
    tc_gemm<false, false, false><<<dim3(D_ / 128, CAP_ / 128, E_), 256, TC_SMEM>>>(
        hbh, hbl, w2, b2, nullptr, eo, nullptr, nullptr, cnt, F_, D_,
        (long)CAP_ * F_ / 2, (long)F_ * D_, (long)D_, (long)CAP_ * D_);

    // 9) shared expert
    tc_gemm<true, false, true><<<dim3(FS_ / 128, T_ / 128, 1), 256, TC_SMEM>>>(
        xn2h, xn2l, ws1, bs1, nullptr, nullptr, shhh, shhl, nullptr,
        D_, FS_, 0, 0, 0, 0);
    tc_gemm<false, false, false><<<dim3(D_ / 128, T_ / 128, 1), 256, TC_SMEM>>>(
        shhh, shhl, ws2, bs2, nullptr, shout, nullptr, nullptr, nullptr,
        FS_, D_, 0, 0, 0, 0);

    // 10) combine
    combine_kernel<<<T_, 256>>>(x2, shout, eo, eidx, pos, gate, out);
}

// round 15
// speedup vs baseline: 1.4343x; 1.0043x over previous
#include <cuda_runtime.h>
#include <cuda_bf16.h>
#include <math.h>
#include <stdint.h>

#define B_    4
#define S_    2048
#define D_    1024
#define H_    16
#define HD_   64
#define E_    8
#define F_    4096
#define FS_   2048
#define T_    8192
#define CAP_  2560
#define KT_   16384   // K * T slots

// ---------------- scratch (static device globals; no allocations) ----------
__device__ float g_vf  [T_ * D_];         // V projection (fp32, pre-transpose)
__device__ float g_x2  [T_ * D_];
__device__ float g_xn2 [T_ * D_];
__device__ float g_eo  [E_ * CAP_ * D_];
__device__ float g_shout[T_ * D_];
__device__ float g_bqk [2 * D_];
__device__ float g_wqk2[2 * D_ * D_];     // contiguous fp32 q,k weights
__device__ int   g_eidx[KT_];
__device__ int   g_pos [KT_];
__device__ int   g_cnt [E_];
__device__ float g_gate[KT_];
// bf16 hi/lo plane tensors (u32 = bf16x2 over a k-pair)
__device__ uint32_t g_xn1h [T_ * D_ / 2],        g_xn1l [T_ * D_ / 2];
__device__ uint32_t g_qkh  [T_ * D_],            g_qkl  [T_ * D_];   // q|k planes
__device__ uint32_t g_vth  [T_ * D_ / 2],        g_vtl  [T_ * D_ / 2];
__device__ uint32_t g_attnh[T_ * D_ / 2],        g_attnl[T_ * D_ / 2];
__device__ uint32_t g_xn2h [T_ * D_ / 2],        g_xn2l [T_ * D_ / 2];
__device__ uint32_t g_disph[E_ * CAP_ * D_ / 2], g_displ[E_ * CAP_ * D_ / 2];
__device__ uint32_t g_hbh  [E_ * CAP_ * F_ / 2], g_hbl  [E_ * CAP_ * F_ / 2];
__device__ uint32_t g_shhh [T_ * FS_ / 2],       g_shhl [T_ * FS_ / 2];

// ---------------- helpers ---------------------------------------------------
__device__ __forceinline__ void split2(float x, float y,
                                       uint32_t& hi, uint32_t& lo)
{
    __nv_bfloat16 hx = __float2bfloat16(x);
    __nv_bfloat16 hy = __float2bfloat16(y);
    float rx = x - __bfloat162float(hx);
    float ry = y - __bfloat162float(hy);
    __nv_bfloat162 h2; h2.x = hx; h2.y = hy;
    __nv_bfloat162 l2; l2.x = __float2bfloat16(rx); l2.y = __float2bfloat16(ry);
    hi = *(uint32_t*)&h2;
    lo = *(uint32_t*)&l2;
}

__device__ __forceinline__ void mma16(float* acc,
                                      uint32_t a0, uint32_t a1, uint32_t a2, uint32_t a3,
                                      uint32_t b0, uint32_t b1)
{
    asm("mma.sync.aligned.m16n8k16.row.col.f32.bf16.bf16.f32 "
        "{%0,%1,%2,%3},{%4,%5,%6,%7},{%8,%9},{%0,%1,%2,%3};"
        : "+f"(acc[0]), "+f"(acc[1]), "+f"(acc[2]), "+f"(acc[3])
        : "r"(a0), "r"(a1), "r"(a2), "r"(a3), "r"(b0), "r"(b1));
}

__device__ __forceinline__ void ldsm4(uint32_t& r0, uint32_t& r1,
                                      uint32_t& r2, uint32_t& r3, uint32_t addr)
{
    asm volatile("ldmatrix.sync.aligned.m8n8.x4.shared.b16 {%0,%1,%2,%3}, [%4];"
                 : "=r"(r0), "=r"(r1), "=r"(r2), "=r"(r3) : "r"(addr));
}

__device__ __forceinline__ void cpasync16(uint32_t dst, const void* src)
{
    asm volatile("cp.async.cg.shared.global [%0], [%1], 16;"
                 :: "r"(dst), "l"(src));
}
#define CP_COMMIT() asm volatile("cp.async.commit_group;" ::: "memory")
#define CP_WAIT0()  asm volatile("cp.async.wait_group 0;" ::: "memory")

// ---------------- QK weight/bias concat -------------------------------------
__global__ void __launch_bounds__(256) wconcat2_kernel(
    const float* __restrict__ a, const float* __restrict__ b,
    float* __restrict__ out)
{
    const long i = (long)blockIdx.x * 1024 + threadIdx.x * 4;
    const float* src = blockIdx.y == 0 ? a : b;
    *(float4*)&out[(long)blockIdx.y * D_ * D_ + i] = *(const float4*)&src[i];
}
__global__ void __launch_bounds__(256) concat2_kernel(
    const float* __restrict__ a, const float* __restrict__ b,
    float* __restrict__ out)
{
    const int i = blockIdx.x * 256 + threadIdx.x;
    out[blockIdx.y * D_ + i] = (blockIdx.y == 0 ? a : b)[i];
}

// ---------------- bf16x3 tensor-core GEMM (round-13 proven) ----------------
#define APW  20
#define BPW  136
#define AWu  (128 * APW)
#define BWu  (16 * BPW)
#define STW  (2 * AWu + 2 * BWu)
#define TC_SMEM (2 * STW * 4)

#define OF_AH 0
#define OF_AL AWu
#define OF_BH (2 * AWu)
#define OF_BL (2 * AWu + BWu)

__device__ __forceinline__ void fillA(
    uint32_t sb, const uint32_t* __restrict__ Ah, const uint32_t* __restrict__ Al,
    int kt, int K2, int m0, int tid)
{
    #pragma unroll
    for (int i = 0; i < 2; i++) {
        const int lin = i * 256 + tid;
        const int row = lin >> 2, ch = (lin & 3) * 4;
        const long src = (long)(m0 + row) * K2 + kt * 16 + ch;
        const uint32_t d = sb + (uint32_t)(row * APW + ch) * 4;
        cpasync16(d + OF_AH * 4, Ah + src);
        cpasync16(d + OF_AL * 4, Al + src);
    }
}

__device__ __forceinline__ void loadB(
    const float* __restrict__ Bw, int kt, int N, int n0, int tid,
    float4 r0[2], float4 r1[2])
{
    const int kp = tid >> 5;
    const int n4 = (tid & 31) * 4;
    #pragma unroll
    for (int i = 0; i < 2; i++) {
        const long k0 = (long)(kt * 32 + 2 * (kp + i * 8));
        r0[i] = *(const float4*)(Bw + k0 * N + n0 + n4);
        r1[i] = *(const float4*)(Bw + (k0 + 1) * N + n0 + n4);
    }
}

__device__ __forceinline__ void stsB(uint32_t sb, int tid,
                                     const float4 r0[2], const float4 r1[2])
{
    const int kp = tid >> 5;
    const int n4 = (tid & 31) * 4;
    #pragma unroll
    for (int i = 0; i < 2; i++) {
        const int kpi = kp + i * 8;
        uint32_t h[4], l[4];
        split2(r0[i].x, r1[i].x, h[0], l[0]);
        split2(r0[i].y, r1[i].y, h[1], l[1]);
        split2(r0[i].z, r1[i].z, h[2], l[2]);
        split2(r0[i].w, r1[i].w, h[3], l[3]);
        const uint32_t off = sb + (uint32_t)(kpi * BPW + n4) * 4;
        asm volatile("st.shared.v4.b32 [%0], {%1,%2,%3,%4};"
            :: "r"(off + OF_BH * 4), "r"(h[0]), "r"(h[1]), "r"(h[2]), "r"(h[3]));
        asm volatile("st.shared.v4.b32 [%0], {%1,%2,%3,%4};"
            :: "r"(off + OF_BL * 4), "r"(l[0]), "r"(l[1]), "r"(l[2]), "r"(l[3]));
    }
}

__device__ __forceinline__ void kslice_mma(
    const uint32_t* __restrict__ buf, uint32_t sb, int kp0,
    int wm, int wn, int g, int t, uint32_t a_lo, float acc[4][4][4])
{
    const uint32_t* Bh = buf + OF_BH;
    const uint32_t* Bl = buf + OF_BL;

    uint32_t bh[4][2], bl[4][2];
    #pragma unroll
    for (int nt = 0; nt < 4; nt++) {
        const int col = wn * 32 + nt * 8 + g;
        bh[nt][0] = Bh[(kp0 + t)     * BPW + col];
        bh[nt][1] = Bh[(kp0 + t + 4) * BPW + col];
        bl[nt][0] = Bl[(kp0 + t)     * BPW + col];
        bl[nt][1] = Bl[(kp0 + t + 4) * BPW + col];
    }
    #pragma unroll
    for (int mt = 0; mt < 4; mt++) {
        const uint32_t abase = sb + (uint32_t)(((wm * 64 + mt * 16) * APW + kp0) * 4) + a_lo;
        uint32_t ah0, ah1, ah2, ah3, al0, al1, al2, al3;
        ldsm4(ah0, ah1, ah2, ah3, abase + OF_AH * 4);
        ldsm4(al0, al1, al2, al3, abase + OF_AL * 4);
        #pragma unroll
        for (int nt = 0; nt < 4; nt++)
            mma16(acc[mt][nt], ah0, ah1, ah2, ah3, bh[nt][0], bh[nt][1]);
        #pragma unroll
        for (int nt = 0; nt < 4; nt++)
            mma16(acc[mt][nt], ah0, ah1, ah2, ah3, bl[nt][0], bl[nt][1]);
        #pragma unroll
        for (int nt = 0; nt < 4; nt++)
            mma16(acc[mt][nt], al0, al1, al2, al3, bh[nt][0], bh[nt][1]);
    }
}

template<bool GELU, bool RES, bool SPLITOUT>
__global__ void __launch_bounds__(256, 2) tc_gemm(
    const uint32_t* __restrict__ Ah, const uint32_t* __restrict__ Al,
    const float* __restrict__ Bw,
    const float* __restrict__ bias, const float* __restrict__ res,
    float* __restrict__ C, uint32_t* __restrict__ Ch, uint32_t* __restrict__ Cl,
    const int* __restrict__ rowcnt,
    int Kd, int N, long sA, long sB, long sBias, long sC)
{
    extern __shared__ uint32_t smw[];
    const uint32_t sbase = (uint32_t)__cvta_generic_to_shared(smw);
    const int tid = threadIdx.x, wid = tid >> 5, lane = tid & 31;
    const int g = lane >> 2, t = lane & 3;
    const int wm = wid & 1, wn = wid >> 1;
    const int bz = blockIdx.z;
    const int m0 = blockIdx.y * 128, n0 = blockIdx.x * 128;
    if (rowcnt != nullptr && m0 >= __ldg(&rowcnt[bz])) return;

    Ah += bz * sA; Al += bz * sA;
    Bw += bz * sB;
    bias += bz * sBias;
    if (SPLITOUT) { Ch += bz * sC; Cl += bz * sC; }
    else          { C  += bz * sC; }
    const int K2 = Kd >> 1;
    const int NT = Kd >> 5;

    const uint32_t a_lo = (uint32_t)(((lane & 15) * APW + ((lane >> 4) << 2)) * 4);

    float acc[4][4][4];
    #pragma unroll
    for (int mt = 0; mt < 4; mt++)
        #pragma unroll
        for (int nt = 0; nt < 4; nt++)
            #pragma unroll
            for (int c = 0; c < 4; c++) acc[mt][nt][c] = 0.0f;

    float4 br0[2], br1[2];
    fillA(sbase, Ah, Al, 0, K2, m0, tid);
    CP_COMMIT();
    loadB(Bw, 0, N, n0, tid, br0, br1);
    stsB(sbase, tid, br0, br1);

    int st = 0;
    for (int kt = 0; kt < NT; kt++) {
        CP_WAIT0();
        __syncthreads();
        if (kt + 1 < NT) {
            fillA(sbase + (st ^ 1) * (STW * 4), Ah, Al, kt + 1, K2, m0, tid);
            loadB(Bw, kt + 1, N, n0, tid, br0, br1);
        }
        CP_COMMIT();
        const uint32_t* buf = smw + st * STW;
        const uint32_t sb = sbase + st * (STW * 4);
        kslice_mma(buf, sb, 0, wm, wn, g, t, a_lo, acc);
        kslice_mma(buf, sb, 8, wm, wn, g, t, a_lo, acc);
        if (kt + 1 < NT)
            stsB(sbase + (st ^ 1) * (STW * 4), tid, br0, br1);
        st ^= 1;
    }

    // ---- epilogue ----
    #pragma unroll
    for (int mt = 0; mt < 4; mt++) {
        const int row = m0 + wm * 64 + mt * 16 + g;
        #pragma unroll
        for (int nt = 0; nt < 4; nt++) {
            const int col = n0 + wn * 32 + nt * 8 + t * 2;
            const float b0v = bias[col], b1v = bias[col + 1];
            float v0 = acc[mt][nt][0] + b0v;
            float v1 = acc[mt][nt][1] + b1v;
            float v2 = acc[mt][nt][2] + b0v;
            float v3 = acc[mt][nt][3] + b1v;
            if (GELU) {
                v0 *= normcdff(v0); v1 *= normcdff(v1);
                v2 *= normcdff(v2); v3 *= normcdff(v3);
            }
            if (SPLITOUT) {
                uint32_t h0, l0, h1, l1;
                split2(v0, v1, h0, l0);
                split2(v2, v3, h1, l1);
                const long p0 = (long)row * (N >> 1) + (col >> 1);
                const long p1 = (long)(row + 8) * (N >> 1) + (col >> 1);
                Ch[p0] = h0; Cl[p0] = l0;
                Ch[p1] = h1; Cl[p1] = l1;
            } else {
                const long o0 = (long)row * N + col;
                const long o1 = (long)(row + 8) * N + col;
                if (RES) {
                    const float2 r0 = *(const float2*)&res[o0];
                    const float2 r1 = *(const float2*)&res[o1];
                    v0 += r0.x; v1 += r0.y; v2 += r1.x; v3 += r1.y;
                }
                float2 w0; w0.x = v0; w0.y = v1;
                float2 w1; w1.x = v2; w1.y = v3;
                *(float2*)&C[o0] = w0;
                *(float2*)&C[o1] = w1;
            }
        }
    }
}

// ---------------- V transpose + split: vf[b,s,h,hd] -> planes [bh*64+hd][s/2]
__global__ void __launch_bounds__(256) transpose_v_split(
    const float* __restrict__ v, uint32_t* __restrict__ vth,
    uint32_t* __restrict__ vtl)
{
    __shared__ float tile[32][33];
    const int bh = blockIdx.z;
    const int b = bh >> 4, h = bh & 15;
    const int s0 = blockIdx.x * 32, d0 = blockIdx.y * 32;
    const int tx = threadIdx.x & 31, ty = threadIdx.x >> 5;
    #pragma unroll
    for (int i = 0; i < 32; i += 8)
        tile[ty + i][tx] = v[(long)(b * S_ + s0 + ty + i) * D_ + h * 64 + d0 + tx];
    __syncthreads();
    #pragma unroll
    for (int i = 0; i < 2; i++) {
        const int lin = i * 256 + threadIdx.x;
        const int hd = lin >> 4;            // 0..31
        const int sp = lin & 15;            // s-pair 0..15
        const float a = tile[2 * sp][hd];
        const float c = tile[2 * sp + 1][hd];
        uint32_t hh, ll;
        split2(a, c, hh, ll);
        const long dst = ((long)bh * 64 + d0 + hd) * (S_ / 2) + (s0 >> 1) + sp;
        vth[dst] = hh;
        vtl[dst] = ll;
    }
}

// ---------------- Flash attention, bf16x3, pre-split inputs ----------------
#define QP 72
#define SM_QH 0
#define SM_QL (128 * QP)
#define SM_KH (2 * 128 * QP)
#define SM_KL (SM_KH + 64 * QP)
#define SM_VH (SM_KL + 64 * QP)
#define SM_VL (SM_VH + 64 * QP)
#define SM_END (SM_VL + 64 * QP)
#define ATT_SMEM (SM_END * 2 + 128)

__global__ void __launch_bounds__(256) attn_mma(
    const uint32_t* __restrict__ qkh, const uint32_t* __restrict__ qkl,
    const uint32_t* __restrict__ vth, const uint32_t* __restrict__ vtl,
    const unsigned char* __restrict__ maskg,
    uint32_t* __restrict__ oh, uint32_t* __restrict__ ol)
{
    extern __shared__ uint16_t sm16[];
    char* ms = (char*)(sm16 + SM_END);

    const int b = blockIdx.z, h = blockIdx.y, q0 = blockIdx.x * 128;
    const int tid = threadIdx.x, wq = tid >> 5, lane = tid & 31;
    const int g = lane >> 2, t4 = lane & 3;
    const float NEG = -3.402823466e38f;
    const uint32_t* kh = qkh + (long)T_ * (D_ / 2);   // k planes follow q
    const uint32_t* kl = qkl + (long)T_ * (D_ / 2);

    // ---- Q tile: copy pre-split planes (128 rows x 32 u32 per plane) ----
    #pragma unroll
    for (int i = 0; i < 4; i++) {
        const int lin = i * 256 + tid;
        const int row = lin >> 3, ch = (lin & 7) * 4;
        const long src = (long)(b * S_ + q0 + row) * (D_ / 2) + h * 32 + ch;
        *(uint4*)&sm16[SM_QH + row * QP + 2 * ch] = *(const uint4*)(qkh + src);
        *(uint4*)&sm16[SM_QL + row * QP + 2 * ch] = *(const uint4*)(qkl + src);
    }
    __syncthreads();

    uint32_t qfh[4][4], qfl[4][4];
    {
        const int qr = wq * 16 + g;
        #pragma unroll
        for (int ks = 0; ks < 4; ks++) {
            const int kc = ks * 16 + 2 * t4;
            qfh[ks][0] = *(const uint32_t*)&sm16[SM_QH + qr * QP + kc];
            qfh[ks][1] = *(const uint32_t*)&sm16[SM_QH + (qr + 8) * QP + kc];
            qfh[ks][2] = *(const uint32_t*)&sm16[SM_QH + qr * QP + kc + 8];
            qfh[ks][3] = *(const uint32_t*)&sm16[SM_QH + (qr + 8) * QP + kc + 8];
            qfl[ks][0] = *(const uint32_t*)&sm16[SM_QL + qr * QP + kc];
            qfl[ks][1] = *(const uint32_t*)&sm16[SM_QL + (qr + 8) * QP + kc];
            qfl[ks][2] = *(const uint32_t*)&sm16[SM_QL + qr * QP + kc + 8];
            qfl[ks][3] = *(const uint32_t*)&sm16[SM_QL + (qr + 8) * QP + kc + 8];
        }
    }

    float m[2], l[2], oacc[8][4];
    m[0] = m[1] = NEG; l[0] = l[1] = 0.0f;
    #pragma unroll
    for (int j = 0; j < 8; j++)
        #pragma unroll
        for (int c = 0; c < 4; c++) oacc[j][c] = 0.0f;

    for (int kt = 0; kt < 32; kt++) {
        const int k0 = kt * 64;
        __syncthreads();
        // ---- K tile: 64 rows x 32 u32/plane (pure copy) ----
        #pragma unroll
        for (int i = 0; i < 2; i++) {
            const int lin = i * 256 + tid;
            const int row = lin >> 3, ch = (lin & 7) * 4;
            const long src = (long)(b * S_ + k0 + row) * (D_ / 2) + h * 32 + ch;
            *(uint4*)&sm16[SM_KH + row * QP + 2 * ch] = *(const uint4*)(kh + src);
            *(uint4*)&sm16[SM_KL + row * QP + 2 * ch] = *(const uint4*)(kl + src);
        }
        // ---- Vt tile: 64 hd rows x 32 u32/plane (pure copy; full coverage) ----
        #pragma unroll
        for (int i = 0; i < 2; i++) {
            const int lin = i * 256 + tid;
            const int row = lin >> 3, ch = (lin & 7) * 4;
            const long src = ((long)(b * 16 + h) * 64 + row) * (S_ / 2) + (k0 >> 1) + ch;
            *(uint4*)&sm16[SM_VH + row * QP + 2 * ch] = *(const uint4*)(vth + src);
            *(uint4*)&sm16[SM_VL + row * QP + 2 * ch] = *(const uint4*)(vtl + src);
        }
        if (tid < 64) ms[tid] = (char)maskg[b * S_ + k0 + tid];
        __syncthreads();

        float sacc[8][4];
        #pragma unroll
        for (int j = 0; j < 8; j++)
            #pragma unroll
            for (int c = 0; c < 4; c++) sacc[j][c] = 0.0f;

        #pragma unroll
        for (int ks = 0; ks < 4; ks++) {
            const int kc = ks * 16 + 2 * t4;
            uint32_t kbh[8][2], kbl[8][2];
            #pragma unroll
            for (int j = 0; j < 8; j++) {
                const int krow = (8 * j + g) * QP;
                kbh[j][0] = *(const uint32_t*)&sm16[SM_KH + krow + kc];
                kbh[j][1] = *(const uint32_t*)&sm16[SM_KH + krow + kc + 8];
                kbl[j][0] = *(const uint32_t*)&sm16[SM_KL + krow + kc];
                kbl[j][1] = *(const uint32_t*)&sm16[SM_KL + krow + kc + 8];
            }
            #pragma unroll
            for (int j = 0; j < 8; j++)
                mma16(sacc[j], qfh[ks][0], qfh[ks][1], qfh[ks][2], qfh[ks][3],
                      kbh[j][0], kbh[j][1]);
            #pragma unroll
            for (int j = 0; j < 8; j++)
                mma16(sacc[j], qfh[ks][0], qfh[ks][1], qfh[ks][2], qfh[ks][3],
                      kbl[j][0], kbl[j][1]);
            #pragma unroll
            for (int j = 0; j < 8; j++)
                mma16(sacc[j], qfl[ks][0], qfl[ks][1], qfl[ks][2], qfl[ks][3],
                      kbh[j][0], kbh[j][1]);
        }

        #pragma unroll
        for (int j = 0; j < 8; j++) {
            const int col = 8 * j + 2 * t4;
            const bool m0k = ms[col] != 0;
            const bool m1k = ms[col + 1] != 0;
            sacc[j][0] = m0k ? NEG : sacc[j][0] * 0.125f;
            sacc[j][1] = m1k ? NEG : sacc[j][1] * 0.125f;
            sacc[j][2] = m0k ? NEG : sacc[j][2] * 0.125f;
            sacc[j][3] = m1k ? NEG : sacc[j][3] * 0.125f;
        }

        #pragma unroll
        for (int r = 0; r < 2; r++) {
            float rmax = NEG;
            #pragma unroll
            for (int j = 0; j < 8; j++) {
                rmax = fmaxf(rmax, sacc[j][2 * r]);
                rmax = fmaxf(rmax, sacc[j][2 * r + 1]);
            }
            rmax = fmaxf(rmax, __shfl_xor_sync(0xffffffffu, rmax, 1));
            rmax = fmaxf(rmax, __shfl_xor_sync(0xffffffffu, rmax, 2));
            const float mnew = fmaxf(m[r], rmax);
            const float corr = expf(m[r] - mnew);
            float rsum = 0.0f;
            #pragma unroll
            for (int j = 0; j < 8; j++) {
                float p0 = expf(sacc[j][2 * r]     - mnew);
                float p1 = expf(sacc[j][2 * r + 1] - mnew);
                sacc[j][2 * r] = p0; sacc[j][2 * r + 1] = p1;
                rsum += p0 + p1;
            }
            rsum += __shfl_xor_sync(0xffffffffu, rsum, 1);
            rsum += __shfl_xor_sync(0xffffffffu, rsum, 2);
            l[r] = l[r] * corr + rsum;
            m[r] = mnew;
            #pragma unroll
            for (int j = 0; j < 8; j++) {
                oacc[j][2 * r]     *= corr;
                oacc[j][2 * r + 1] *= corr;
            }
        }

        #pragma unroll
        for (int ks = 0; ks < 4; ks++) {
            const int j0 = 2 * ks, j1 = 2 * ks + 1;
            uint32_t ph0, pl0, ph1, pl1, ph2, pl2, ph3, pl3;
            split2(sacc[j0][0], sacc[j0][1], ph0, pl0);
            split2(sacc[j0][2], sacc[j0][3], ph1, pl1);
            split2(sacc[j1][0], sacc[j1][1], ph2, pl2);
            split2(sacc[j1][2], sacc[j1][3], ph3, pl3);
            const int kc = ks * 16 + 2 * t4;
            uint32_t vfh[8][2], vfl[8][2];
            #pragma unroll
            for (int j = 0; j < 8; j++) {
                const int vrow = (8 * j + g) * QP;
                vfh[j][0] = *(const uint32_t*)&sm16[SM_VH + vrow + kc];
                vfh[j][1] = *(const uint32_t*)&sm16[SM_VH + vrow + kc + 8];
                vfl[j][0] = *(const uint32_t*)&sm16[SM_VL + vrow + kc];
                vfl[j][1] = *(const uint32_t*)&sm16[SM_VL + vrow + kc + 8];
            }
            #pragma unroll
            for (int j = 0; j < 8; j++)
                mma16(oacc[j], ph0, ph1, ph2, ph3, vfh[j][0], vfh[j][1]);
            #pragma unroll
            for (int j = 0; j < 8; j++)
                mma16(oacc[j], ph0, ph1, ph2, ph3, vfl[j][0], vfl[j][1]);
            #pragma unroll
            for (int j = 0; j < 8; j++)
                mma16(oacc[j], pl0, pl1, pl2, pl3, vfh[j][0], vfh[j][1]);
        }
    }

    const float inv0 = 1.0f / l[0], inv1 = 1.0f / l[1];
    const int row0 = q0 + wq * 16 + g;
    #pragma unroll
    for (int j = 0; j < 8; j++) {
        const int col = h * 64 + 8 * j + 2 * t4;
        uint32_t h0, l0, h1, l1;
        split2(oacc[j][0] * inv0, oacc[j][1] * inv0, h0, l0);
        split2(oacc[j][2] * inv1, oacc[j][3] * inv1, h1, l1);
        const long p0 = (long)(b * S_ + row0) * (D_ / 2) + (col >> 1);
        const long p1 = (long)(b * S_ + row0 + 8) * (D_ / 2) + (col >> 1);
        oh[p0] = h0; ol[p0] = l0;
        oh[p1] = h1; ol[p1] = l1;
    }
}

// ---------------- LayerNorm (writes split planes; optional fp32) -----------
template<bool F32OUT>
__global__ void __launch_bounds__(256) ln_kernel(const float* __restrict__ x,
                                                 const float* __restrict__ g,
                                                 const float* __restrict__ b,
                                                 float* __restrict__ outf,
                                                 uint32_t* __restrict__ outh,
                                                 uint32_t* __restrict__ outl)
{
    const int row = blockIdx.x;
    const int tid = threadIdx.x;
    const float4 v = ((const float4*)(x + (long)row * D_))[tid];

    __shared__ float red[256];
    __shared__ float s_mu, s_rstd;

    float s = v.x + v.y + v.z + v.w;
    red[tid] = s; __syncthreads();
    for (int o = 128; o > 0; o >>= 1) {
        if (tid < o) red[tid] += red[tid + o];
        __syncthreads();
    }
    if (tid == 0) s_mu = red[0] * (1.0f / D_);
    __syncthreads();
    const float mu = s_mu;

    float dx0 = v.x - mu, dx1 = v.y - mu, dx2 = v.z - mu, dx3 = v.w - mu;
    float sq = dx0*dx0 + dx1*dx1 + dx2*dx2 + dx3*dx3;
    red[tid] = sq; __syncthreads();
    for (int o = 128; o > 0; o >>= 1) {
        if (tid < o) red[tid] += red[tid + o];
        __syncthreads();
    }
    if (tid == 0) s_rstd = rsqrtf(red[0] * (1.0f / D_) + 1e-5f);
    __syncthreads();
    const float rstd = s_rstd;

    const float4 gg = ((const float4*)g)[tid];
    const float4 bb = ((const float4*)b)[tid];
    float4 o4;
    o4.x = dx0 * rstd * gg.x + bb.x;
    o4.y = dx1 * rstd * gg.y + bb.y;
    o4.z = dx2 * rstd * gg.z + bb.z;
    o4.w = dx3 * rstd * gg.w + bb.w;
    if (F32OUT)
        ((float4*)(outf + (long)row * D_))[tid] = o4;
    uint32_t h0, l0, h1, l1;
    split2(o4.x, o4.y, h0, l0);
    split2(o4.z, o4.w, h1, l1);
    uint2 hv; hv.x = h0; hv.y = h1;
    uint2 lv; lv.x = l0; lv.y = l1;
    *(uint2*)&outh[(long)row * (D_ / 2) + tid * 2] = hv;
    *(uint2*)&outl[(long)row * (D_ / 2) + tid * 2] = lv;
}

// ---------------- Router --------------------------------------------------
__global__ void __launch_bounds__(256) router_kernel(
    const float* __restrict__ xn, const float* __restrict__ wr,
    int* __restrict__ eidx, float* __restrict__ gate)
{
    const int warp = threadIdx.x >> 5, lane = threadIdx.x & 31;
    const int t = blockIdx.x * 8 + warp;
    const float* xr = xn + (long)t * D_;

    float a[E_];
    #pragma unroll
    for (int e = 0; e < E_; e++) a[e] = 0.0f;
    for (int d = lane; d < D_; d += 32) {
        const float xv = xr[d];
        const float* w = wr + d * E_;
        #pragma unroll
        for (int e = 0; e < E_; e++) a[e] += xv * w[e];
    }
    #pragma unroll
    for (int e = 0; e < E_; e++)
        #pragma unroll
        for (int o = 16; o > 0; o >>= 1)
            a[e] += __shfl_xor_sync(0xffffffffu, a[e], o);

    if (lane == 0) {
        float mx = a[0];
        #pragma unroll
        for (int e = 1; e < E_; e++) mx = fmaxf(mx, a[e]);
        float ex[E_];
        #pragma unroll
        for (int e = 0; e < E_; e++) ex[e] = expf(a[e] - mx);
        int i0 = 0; float v0 = ex[0];
        #pragma unroll
        for (int e = 1; e < E_; e++) if (ex[e] > v0) { v0 = ex[e]; i0 = e; }
        int i1 = -1; float v1 = -1.0f;
        #pragma unroll
        for (int e = 0; e < E_; e++)
            if (e != i0 && ex[e] > v1) { v1 = ex[e]; i1 = e; }
        const float inv = 1.0f / (v0 + v1);
        eidx[t]       = i0; gate[t]       = v0 * inv;
        eidx[T_ + t]  = i1; gate[T_ + t]  = v1 * inv;
    }
}

// ---------------- Single-pass slot-major capacity scan ---------------------
__global__ void __launch_bounds__(256) scan_kernel(const int* __restrict__ eidx,
                                                   int* __restrict__ pos,
                                                   int* __restrict__ cnt)
{
    const int e = blockIdx.x;
    const int tid = threadIdx.x;
    const int base = tid * 64;

    int lc = 0;
    #pragma unroll 8
    for (int j = 0; j < 64; j++)
        lc += (eidx[base + j] == e) ? 1 : 0;

    __shared__ int sd[256];
    sd[tid] = lc;
    __syncthreads();
    for (int o = 1; o < 256; o <<= 1) {
        int v = (tid >= o) ? sd[tid - o] : 0;
        __syncthreads();
        sd[tid] += v;
        __syncthreads();
    }
    int run = sd[tid] - lc;
    #pragma unroll 8
    for (int j = 0; j < 64; j++) {
        if (eidx[base + j] == e) pos[base + j] = run++;
    }
    if (tid == 255) cnt[e] = sd[255] < CAP_ ? sd[255] : CAP_;
}

__global__ void __launch_bounds__(256) dispatch_kernel(
    const uint32_t* __restrict__ xnh, const uint32_t* __restrict__ xnl,
    const int* __restrict__ eidx, const int* __restrict__ pos,
    uint32_t* __restrict__ dh, uint32_t* __restrict__ dl)
{
    const int s = blockIdx.x;
    const int p = pos[s];
    if (p >= CAP_) return;
    const int e = eidx[s];
    const int t = s & (T_ - 1);
    const long src = (long)t * (D_ / 2);
    const long dst = ((long)e * CAP_ + p) * (D_ / 2);
    const uint2* sh = (const uint2*)(xnh + src);
    const uint2* sl = (const uint2*)(xnl + src);
    uint2* th = (uint2*)(dh + dst);
    uint2* tl = (uint2*)(dl + dst);
    th[threadIdx.x] = sh[threadIdx.x];
    tl[threadIdx.x] = sl[threadIdx.x];
}

__global__ void __launch_bounds__(256) combine_kernel(
    const float* __restrict__ x2, const float* __restrict__ shout,
    const float* __restrict__ eo, const int* __restrict__ eidx,
    const int* __restrict__ pos, const float* __restrict__ gate,
    float* __restrict__ out)
{
    const int t = blockIdx.x;
    const int p0 = pos[t], p1 = pos[T_ + t];
    const float g0 = gate[t]      * (p0 < CAP_ ? 1.0f : 0.0f);
    const float g1 = gate[T_ + t] * (p1 < CAP_ ? 1.0f : 0.0f);
    const long o0 = ((long)eidx[t]      * CAP_ + min(p0, CAP_ - 1)) * D_;
    const long o1 = ((long)eidx[T_ + t] * CAP_ + min(p1, CAP_ - 1)) * D_;

    const int c = threadIdx.x;
    float4 a = ((const float4*)(x2 + (long)t * D_))[c];
    float4 s = ((const float4*)(shout + (long)t * D_))[c];
    float4 r0 = ((const float4*)(eo + o0))[c];
    float4 r1 = ((const float4*)(eo + o1))[c];
    float4 o;
    o.x = a.x + s.x + g0 * r0.x + g1 * r1.x;
    o.y = a.y + s.y + g0 * r0.y + g1 * r1.y;
    o.z = a.z + s.z + g0 * r0.z + g1 * r1.z;
    o.w = a.w + s.w + g0 * r0.w + g1 * r1.w;
    ((float4*)(out + (long)t * D_))[c] = o;
}

// ---------------------------------------------------------------------------
extern "C" void kernel_launch(void* const* d_in, const int* in_sizes, int n_in,
                              void* d_out, int out_size)
{
    const float* x   = (const float*)d_in[0];
    const unsigned char* mask = (const unsigned char*)d_in[1];
    const float* ln1g = (const float*)d_in[2];
    const float* ln1b = (const float*)d_in[3];
    const float* wq = (const float*)d_in[4];  const float* bq = (const float*)d_in[5];
    const float* wk = (const float*)d_in[6];  const float* bk = (const float*)d_in[7];
    const float* wv = (const float*)d_in[8];  const float* bv = (const float*)d_in[9];
    const float* wo = (const float*)d_in[10]; const float* bo = (const float*)d_in[11];
    const float* ln2g = (const float*)d_in[12];
    const float* ln2b = (const float*)d_in[13];
    const float* wr = (const float*)d_in[14];
    const float* w1 = (const float*)d_in[15]; const float* b1 = (const float*)d_in[16];
    const float* w2 = (const float*)d_in[17]; const float* b2 = (const float*)d_in[18];
    const float* ws1 = (const float*)d_in[19]; const float* bs1 = (const float*)d_in[20];
    const float* ws2 = (const float*)d_in[21]; const float* bs2 = (const float*)d_in[22];
    float* out = (float*)d_out;

    float *vf, *x2, *xn2, *eo, *shout, *gate, *bqk, *wqk2;
    int *eidx, *pos, *cnt;
    uint32_t *xn1h, *xn1l, *qkh, *qkl, *vth, *vtl, *attnh, *attnl, *xn2h, *xn2l;
    uint32_t *disph, *displ, *hbh, *hbl, *shhh, *shhl;

    cudaGetSymbolAddress((void**)&vf,   g_vf);
    cudaGetSymbolAddress((void**)&x2,   g_x2);
    cudaGetSymbolAddress((void**)&xn2,  g_xn2);
    cudaGetSymbolAddress((void**)&eo,   g_eo);
    cudaGetSymbolAddress((void**)&shout,g_shout);
    cudaGetSymbolAddress((void**)&bqk,  g_bqk);
    cudaGetSymbolAddress((void**)&wqk2, g_wqk2);
    cudaGetSymbolAddress((void**)&eidx, g_eidx);
    cudaGetSymbolAddress((void**)&pos,  g_pos);
    cudaGetSymbolAddress((void**)&cnt,  g_cnt);
    cudaGetSymbolAddress((void**)&gate, g_gate);
    cudaGetSymbolAddress((void**)&xn1h, g_xn1h);  cudaGetSymbolAddress((void**)&xn1l, g_xn1l);
    cudaGetSymbolAddress((void**)&qkh,  g_qkh);   cudaGetSymbolAddress((void**)&qkl,  g_qkl);
    cudaGetSymbolAddress((void**)&vth,  g_vth);   cudaGetSymbolAddress((void**)&vtl,  g_vtl);
    cudaGetSymbolAddress((void**)&attnh,g_attnh); cudaGetSymbolAddress((void**)&attnl,g_attnl);
    cudaGetSymbolAddress((void**)&xn2h, g_xn2h);  cudaGetSymbolAddress((void**)&xn2l, g_xn2l);
    cudaGetSymbolAddress((void**)&disph,g_disph); cudaGetSymbolAddress((void**)&displ,g_displ);
    cudaGetSymbolAddress((void**)&hbh,  g_hbh);   cudaGetSymbolAddress((void**)&hbl,  g_hbl);
    cudaGetSymbolAddress((void**)&shhh, g_shhh);  cudaGetSymbolAddress((void**)&shhl, g_shhl);

    cudaFuncSetAttribute(attn_mma,
                         cudaFuncAttributeMaxDynamicSharedMemorySize, ATT_SMEM);
    cudaFuncSetAttribute(tc_gemm<false, false, false>,
                         cudaFuncAttributeMaxDynamicSharedMemorySize, TC_SMEM);
    cudaFuncSetAttribute(tc_gemm<false, false, true>,
                         cudaFuncAttributeMaxDynamicSharedMemorySize, TC_SMEM);
    cudaFuncSetAttribute(tc_gemm<false, true, false>,
                         cudaFuncAttributeMaxDynamicSharedMemorySize, TC_SMEM);
    cudaFuncSetAttribute(tc_gemm<true, false, true>,
                         cudaFuncAttributeMaxDynamicSharedMemorySize, TC_SMEM);

    // 0) concat q,k weights + biases
    wconcat2_kernel<<<dim3(D_ * D_ / 1024, 2), 256>>>(wq, wk, wqk2);
    concat2_kernel<<<dim3(D_/256, 2), 256>>>(bq, bk, bqk);

    // 1) LN1 -> split planes
    ln_kernel<false><<<T_, 256>>>(x, ln1g, ln1b, nullptr, xn1h, xn1l);

    // 2) Q,K projection (split-plane output); V projection (fp32)
    tc_gemm<false, false, true><<<dim3(D_/128, T_/128, 2), 256, TC_SMEM>>>(
        xn1h, xn1l, wqk2, bqk, nullptr, nullptr, qkh, qkl, nullptr,
        D_, D_, 0, (long)D_ * D_, D_, (long)T_ * D_ / 2);
    tc_gemm<false, false, false><<<dim3(D_/128, T_/128, 1), 256, TC_SMEM>>>(
        xn1h, xn1l, wv, bv, nullptr, vf, nullptr, nullptr, nullptr,
        D_, D_, 0, 0, 0, 0);

    // 3) attention (pre-split inputs)
    transpose_v_split<<<dim3(S_ / 32, 2, B_ * H_), 256>>>(vf, vth, vtl);
    attn_mma<<<dim3(S_ / 128, H_, B_), 256, ATT_SMEM>>>(
        qkh, qkl, vth, vtl, mask, attnh, attnl);

    // 4) O projection + residual -> x2
    tc_gemm<false, true, false><<<dim3(D_/128, T_/128, 1), 256, TC_SMEM>>>(
        attnh, attnl, wo, bo, x, x2, nullptr, nullptr, nullptr,
        D_, D_, 0, 0, 0, 0);

    // 5) LN2
    ln_kernel<true><<<T_, 256>>>(x2, ln2g, ln2b, xn2, xn2h, xn2l);

    // 6) router + single-pass scan
    router_kernel<<<T_ / 8, 256>>>(xn2, wr, eidx, gate);
    scan_kernel<<<E_, 256>>>(eidx, pos, cnt);

    // 7) dispatch (no zeroing needed)
    dispatch_kernel<<<KT_, 256>>>(xn2h, xn2l, eidx, pos, disph, displ);

    // 8) expert FFN (capacity-tile skip via cnt)
    tc_gemm<true, false, true><<<dim3(F_ / 128, CAP_ / 128, E_), 256, TC_SMEM>>>(
        disph, displ, w1, b1, nullptr, nullptr, hbh, hbl, cnt, D_, F_,
        (long)CAP_ * D_ / 2, (long)D_ * F_, (long)F_, (long)CAP_ * F_ / 2);
    tc_gemm<false, false, false><<<dim3(D_ / 128, CAP_ / 128, E_), 256, TC_SMEM>>>(
        hbh, hbl, w2, b2, nullptr, eo, nullptr, nullptr, cnt, F_, D_,
        (long)CAP_ * F_ / 2, (long)F_ * D_, (long)D_, (long)CAP_ * D_);

    // 9) shared expert
    tc_gemm<true, false, true><<<dim3(FS_ / 128, T_ / 128, 1), 256, TC_SMEM>>>(
        xn2h, xn2l, ws1, bs1, nullptr, nullptr, shhh, shhl, nullptr,
        D_, FS_, 0, 0, 0, 0);
    tc_gemm<false, false, false><<<dim3(D_ / 128, T_ / 128, 1), 256, TC_SMEM>>>(
        shhh, shhl, ws2, bs2, nullptr, shout, nullptr, nullptr, nullptr,
        FS_, D_, 0, 0, 0, 0);

    // 10) combine
    combine_kernel<<<T_, 256>>>(x2, shout, eo, eidx, pos, gate, out);
}